// round 3
// baseline (speedup 1.0000x reference)
#include <cuda_runtime.h>
#include <math.h>
#include <stdint.h>

// ---------------- constants ----------------
#define Bdim 8
#define Ndim 1024
#define Ddim 1024
#define Hdim 16
#define DEPTH 64
#define MLPdim 4096
#define ROWS (Bdim * Ndim)          // 8192
#define EPSLN 1e-6f
#define INV_SQRT_DEPTH 0.125f

// ---------------- scratch (static device globals; no allocation) ----------------
__device__ float g_xn[ROWS * Ddim];        // x_norm1 / x_norm2
__device__ float g_q[ROWS * Ddim];         // q, later r
__device__ float g_k[ROWS * Ddim];
__device__ float g_v[ROWS * Ddim];
__device__ float g_ao[ROWS * Ddim];        // attn_out
__device__ float g_mlph[ROWS * MLPdim];
__device__ float g_attn[Bdim * Hdim * Ndim];
__device__ float g_gq[Bdim * Hdim * DEPTH];
__device__ float g_h[Bdim * Ddim];
__device__ float g_scale[Bdim * Ddim];
__device__ float g_shift[Bdim * Ddim];

// ---------------- block reduction helpers ----------------
__device__ __forceinline__ float blockReduceSum(float v, float* smem) {
    #pragma unroll
    for (int o = 16; o; o >>= 1) v += __shfl_xor_sync(0xFFFFFFFFu, v, o);
    int wid = threadIdx.x >> 5;
    if ((threadIdx.x & 31) == 0) smem[wid] = v;
    __syncthreads();
    float r = 0.f;
    if (threadIdx.x < 8) r = smem[threadIdx.x];
    if (threadIdx.x < 8) {
        #pragma unroll
        for (int o = 4; o; o >>= 1) r += __shfl_xor_sync(0xFFu, r, o);
        if (threadIdx.x == 0) smem[0] = r;
    }
    __syncthreads();
    r = smem[0];
    __syncthreads();
    return r;
}

__device__ __forceinline__ float blockReduceMax(float v, float* smem) {
    #pragma unroll
    for (int o = 16; o; o >>= 1) v = fmaxf(v, __shfl_xor_sync(0xFFFFFFFFu, v, o));
    int wid = threadIdx.x >> 5;
    if ((threadIdx.x & 31) == 0) smem[wid] = v;
    __syncthreads();
    float r = -1e30f;
    if (threadIdx.x < 8) r = smem[threadIdx.x];
    if (threadIdx.x < 8) {
        #pragma unroll
        for (int o = 4; o; o >>= 1) r = fmaxf(r, __shfl_xor_sync(0xFFu, r, o));
        if (threadIdx.x == 0) smem[0] = r;
    }
    __syncthreads();
    r = smem[0];
    __syncthreads();
    return r;
}

// ---------------- tf32 helpers ----------------
__device__ __forceinline__ uint32_t f2tf(float f) {
    uint32_t u;
    asm("cvt.rna.tf32.f32 %0, %1;" : "=r"(u) : "f"(f));
    return u;
}
__device__ __forceinline__ uint4 cvt4(float4 v) {
    uint4 o;
    o.x = f2tf(v.x); o.y = f2tf(v.y); o.z = f2tf(v.z); o.w = f2tf(v.w);
    return o;
}
__device__ __forceinline__ void mma_tf32(float* d, const uint32_t* a, const uint32_t* b) {
    asm volatile(
        "mma.sync.aligned.m16n8k8.row.col.f32.tf32.tf32.f32 "
        "{%0,%1,%2,%3},{%4,%5,%6,%7},{%8,%9},{%0,%1,%2,%3};"
        : "+f"(d[0]), "+f"(d[1]), "+f"(d[2]), "+f"(d[3])
        : "r"(a[0]), "r"(a[1]), "r"(a[2]), "r"(a[3]), "r"(b[0]), "r"(b[1]));
}

// ---------------- TF32 tensor-core GEMM ----------------
// C[M,N] = epi(A[M,K] @ W[K,N] + bias)
// EPI: 0 = +bias ; 1 = +bias +res ; 2 = gelu(+bias)
// Block tile 128x128, BK=16, 256 threads (8 warps of 64x32 warp tiles).
#define GBK 16
#define AS_STRIDE 20     // 16 + 4 pad (floats) -> conflict-free frag reads
#define BS_STRIDE 136    // 128 + 8 pad (floats) -> conflict-free frag reads

template <int EPI>
__global__ __launch_bounds__(256, 2)
void mma_gemm(const float* __restrict__ A, const float* __restrict__ W,
              const float* __restrict__ bias, const float* __restrict__ res,
              float* __restrict__ C, int M, int N, int K) {
    __shared__ uint32_t As[2][128 * AS_STRIDE];
    __shared__ uint32_t Bs[2][GBK * BS_STRIDE];

    const int tid = threadIdx.x;
    const int lane = tid & 31;
    const int warp = tid >> 5;
    const int wm = warp >> 2;        // 0..1
    const int wn = warp & 3;         // 0..3
    const int g = lane >> 2;         // 0..7
    const int c = lane & 3;          // 0..3

    // loader indices
    const int aRow = tid >> 2;               // 0..63 (two passes of 64 rows)
    const int aCol = (tid & 3) << 2;         // 0,4,8,12
    const int bK = tid >> 5;                 // 0..7 (two passes of 8 k-rows)
    const int bCol = (tid & 31) << 2;        // 0..124

    const float* Aptr = A + (size_t)(blockIdx.y * 128 + aRow) * K + aCol;
    const float* Bptr = W + (size_t)bK * N + blockIdx.x * 128 + bCol;

    float acc[4][4][4];
    #pragma unroll
    for (int i = 0; i < 4; ++i)
        #pragma unroll
        for (int j = 0; j < 4; ++j)
            #pragma unroll
            for (int q = 0; q < 4; ++q) acc[i][j][q] = 0.f;

    float4 aLd[2], bLd[2];

    // prologue: load tile 0
    aLd[0] = *reinterpret_cast<const float4*>(Aptr);
    aLd[1] = *reinterpret_cast<const float4*>(Aptr + (size_t)64 * K);
    bLd[0] = *reinterpret_cast<const float4*>(Bptr);
    bLd[1] = *reinterpret_cast<const float4*>(Bptr + (size_t)8 * N);
    *reinterpret_cast<uint4*>(&As[0][aRow * AS_STRIDE + aCol]) = cvt4(aLd[0]);
    *reinterpret_cast<uint4*>(&As[0][(aRow + 64) * AS_STRIDE + aCol]) = cvt4(aLd[1]);
    *reinterpret_cast<uint4*>(&Bs[0][bK * BS_STRIDE + bCol]) = cvt4(bLd[0]);
    *reinterpret_cast<uint4*>(&Bs[0][(bK + 8) * BS_STRIDE + bCol]) = cvt4(bLd[1]);
    __syncthreads();

    int cur = 0;
    for (int kt = GBK; kt <= K; kt += GBK) {
        const bool hasNext = (kt < K);
        if (hasNext) {
            aLd[0] = *reinterpret_cast<const float4*>(Aptr + kt);
            aLd[1] = *reinterpret_cast<const float4*>(Aptr + kt + (size_t)64 * K);
            bLd[0] = *reinterpret_cast<const float4*>(Bptr + (size_t)kt * N);
            bLd[1] = *reinterpret_cast<const float4*>(Bptr + (size_t)(kt + 8) * N);
        }

        // compute on buffer `cur`
        const uint32_t* as = As[cur];
        const uint32_t* bs = Bs[cur];
        #pragma unroll
        for (int ks = 0; ks < 2; ++ks) {
            const int k8 = ks * 8;
            uint32_t af[4][4], bf[4][2];
            #pragma unroll
            for (int i = 0; i < 4; ++i) {
                const int m = wm * 64 + i * 16 + g;
                af[i][0] = as[m * AS_STRIDE + k8 + c];
                af[i][1] = as[(m + 8) * AS_STRIDE + k8 + c];
                af[i][2] = as[m * AS_STRIDE + k8 + c + 4];
                af[i][3] = as[(m + 8) * AS_STRIDE + k8 + c + 4];
            }
            #pragma unroll
            for (int j = 0; j < 4; ++j) {
                const int n = wn * 32 + j * 8 + g;
                bf[j][0] = bs[(k8 + c) * BS_STRIDE + n];
                bf[j][1] = bs[(k8 + c + 4) * BS_STRIDE + n];
            }
            #pragma unroll
            for (int i = 0; i < 4; ++i)
                #pragma unroll
                for (int j = 0; j < 4; ++j)
                    mma_tf32(acc[i][j], af[i], bf[j]);
        }

        if (hasNext) {
            const int nxt = cur ^ 1;
            *reinterpret_cast<uint4*>(&As[nxt][aRow * AS_STRIDE + aCol]) = cvt4(aLd[0]);
            *reinterpret_cast<uint4*>(&As[nxt][(aRow + 64) * AS_STRIDE + aCol]) = cvt4(aLd[1]);
            *reinterpret_cast<uint4*>(&Bs[nxt][bK * BS_STRIDE + bCol]) = cvt4(bLd[0]);
            *reinterpret_cast<uint4*>(&Bs[nxt][(bK + 8) * BS_STRIDE + bCol]) = cvt4(bLd[1]);
            __syncthreads();
            cur = nxt;
        }
    }

    // epilogue
    #pragma unroll
    for (int i = 0; i < 4; ++i) {
        const int row0 = blockIdx.y * 128 + wm * 64 + i * 16 + g;
        #pragma unroll
        for (int j = 0; j < 4; ++j) {
            const int col = blockIdx.x * 128 + wn * 32 + j * 8 + 2 * c;
            const float b0 = bias[col], b1 = bias[col + 1];
            #pragma unroll
            for (int half = 0; half < 2; ++half) {
                const int row = row0 + half * 8;
                float v0 = acc[i][j][half * 2 + 0] + b0;
                float v1 = acc[i][j][half * 2 + 1] + b1;
                if (EPI == 1) {
                    const float2 rr = *reinterpret_cast<const float2*>(res + (size_t)row * N + col);
                    v0 += rr.x; v1 += rr.y;
                }
                if (EPI == 2) {
                    v0 = 0.5f * v0 * (1.f + erff(v0 * 0.7071067811865475f));
                    v1 = 0.5f * v1 * (1.f + erff(v1 * 0.7071067811865475f));
                }
                float2 o; o.x = v0; o.y = v1;
                *reinterpret_cast<float2*>(C + (size_t)row * N + col) = o;
            }
        }
    }
}

// ---------------- layernorm (no affine) + per-row scale/shift modulation ----------------
__global__ __launch_bounds__(256)
void ln_mod_kernel(const float* __restrict__ x, const float* __restrict__ scale,
                   const float* __restrict__ shift, float* __restrict__ out) {
    __shared__ float smem[8];
    const int row = blockIdx.x;          // 0..8191
    const int b = row >> 10;
    const int n = row & 1023;
    float4 v = reinterpret_cast<const float4*>(x + (size_t)row * Ddim)[threadIdx.x];
    float s = v.x + v.y + v.z + v.w;
    float mean = blockReduceSum(s, smem) * (1.f / Ddim);
    float dx = v.x - mean, dy = v.y - mean, dz = v.z - mean, dw = v.w - mean;
    float sq = dx * dx + dy * dy + dz * dz + dw * dw;
    float var = blockReduceSum(sq, smem) * (1.f / Ddim);
    float rstd = rsqrtf(var + EPSLN);
    float sc = scale[b * Ddim + n] * rstd;
    float sh = shift[b * Ddim + n];
    float4 o;
    o.x = dx * sc + sh; o.y = dy * sc + sh; o.z = dz * sc + sh; o.w = dw * sc + sh;
    reinterpret_cast<float4*>(out + (size_t)row * Ddim)[threadIdx.x] = o;
}

// ---------------- small conditioning GEMM ----------------
__global__ __launch_bounds__(256)
void small_gemm_kernel(const float* __restrict__ A, const float* __restrict__ W,
                       const float* __restrict__ bias, float* __restrict__ out,
                       int K, int N, int act) {
    const int n = blockIdx.x * 256 + threadIdx.x;
    const int b = blockIdx.y;
    const float* a = A + (size_t)b * K;
    float acc = 0.f;
    for (int k = 0; k < K; ++k) acc = fmaf(a[k], W[(size_t)k * N + n], acc);
    acc += bias[n];
    if (act == 1) acc = fmaxf(acc, 0.f);
    out[(size_t)b * N + n] = acc;
}

// ---------------- q -> attention logits ----------------
__global__ __launch_bounds__(256)
void qa_kernel(const float* __restrict__ q, const float* __restrict__ w,
               const float* __restrict__ bias, float* __restrict__ attn) {
    const int warp = threadIdx.x >> 5;
    const int lane = threadIdx.x & 31;
    const int gi = blockIdx.x * 8 + warp;     // 0 .. B*N*H-1
    const int h = gi & 15;
    const int bn = gi >> 4;                   // b*1024+n
    const float* qr = q + (size_t)bn * Ddim;
    float acc = 0.f;
    #pragma unroll 4
    for (int k = lane; k < Ddim; k += 32) acc = fmaf(qr[k], w[k * Hdim + h], acc);
    #pragma unroll
    for (int o = 16; o; o >>= 1) acc += __shfl_xor_sync(0xFFFFFFFFu, acc, o);
    if (lane == 0) {
        const int b = bn >> 10, n = bn & 1023;
        attn[(size_t)b * Hdim * Ndim + h * Ndim + n] = (acc + bias[h]) * INV_SQRT_DEPTH;
    }
}

// ---------------- softmax over N for each (b,h); also writes attn_maps output ----------------
__global__ __launch_bounds__(256)
void softmax_kernel(float* __restrict__ attn, float* __restrict__ out_attn) {
    __shared__ float smem[8];
    const int row = blockIdx.x;  // 0..127
    float4 v = reinterpret_cast<float4*>(attn + (size_t)row * Ndim)[threadIdx.x];
    float m = fmaxf(fmaxf(v.x, v.y), fmaxf(v.z, v.w));
    m = blockReduceMax(m, smem);
    v.x = __expf(v.x - m); v.y = __expf(v.y - m); v.z = __expf(v.z - m); v.w = __expf(v.w - m);
    float s = v.x + v.y + v.z + v.w;
    s = blockReduceSum(s, smem);
    float inv = 1.f / s;
    v.x *= inv; v.y *= inv; v.z *= inv; v.w *= inv;
    reinterpret_cast<float4*>(attn + (size_t)row * Ndim)[threadIdx.x] = v;
    reinterpret_cast<float4*>(out_attn + (size_t)row * Ndim)[threadIdx.x] = v;
}

// ---------------- global_q[b,h,d] = sum_n attn[b,h,n] * q[b,n,h*64+d] ----------------
__global__ __launch_bounds__(256)
void globalq_kernel(const float* __restrict__ attn, const float* __restrict__ q,
                    float* __restrict__ gq) {
    __shared__ float part[256];
    const int bh = blockIdx.x;           // 0..127
    const int b = bh >> 4, h = bh & 15;
    const int g = threadIdx.x >> 6;      // 0..3
    const int d = threadIdx.x & 63;
    const float* ar = attn + (size_t)bh * Ndim;
    float acc = 0.f;
    for (int n = g; n < Ndim; n += 4)
        acc = fmaf(ar[n], q[((size_t)(b * Ndim + n)) * Ddim + h * DEPTH + d], acc);
    part[threadIdx.x] = acc;
    __syncthreads();
    if (g == 0)
        gq[(size_t)bh * DEPTH + d] = part[d] + part[64 + d] + part[128 + d] + part[192 + d];
}

// ---------------- r = broadcast(global_q) * k * v ----------------
__global__ __launch_bounds__(256)
void r_kernel(const float* __restrict__ gq, const float* __restrict__ k,
              const float* __restrict__ v, float* __restrict__ r) {
    const size_t idx = (size_t)blockIdx.x * 256 + threadIdx.x;
    const int d = (int)(idx & 1023);
    const int b = (int)(idx >> 20);      // / (N*D)
    r[idx] = gq[b * Ddim + d] * k[idx] * v[idx];
}

// ---------------- host launch ----------------
extern "C" void kernel_launch(void* const* d_in, const int* in_sizes, int n_in,
                              void* d_out, int out_size) {
    const float* inputs = (const float*)d_in[0];
    const float* z      = (const float*)d_in[1];
    const float* n1_hw = (const float*)d_in[2];  const float* n1_hb = (const float*)d_in[3];
    const float* n1_gw = (const float*)d_in[4];  const float* n1_gb = (const float*)d_in[5];
    const float* n1_bw = (const float*)d_in[6];  const float* n1_bb = (const float*)d_in[7];
    const float* wq_w  = (const float*)d_in[8];  const float* wq_b  = (const float*)d_in[9];
    const float* wk_w  = (const float*)d_in[10]; const float* wk_b  = (const float*)d_in[11];
    const float* wv_w  = (const float*)d_in[12]; const float* wv_b  = (const float*)d_in[13];
    const float* qa_w  = (const float*)d_in[14]; const float* qa_b  = (const float*)d_in[15];
    const float* out_w = (const float*)d_in[16]; const float* out_b = (const float*)d_in[17];
    const float* n2_hw = (const float*)d_in[18]; const float* n2_hb = (const float*)d_in[19];
    const float* n2_gw = (const float*)d_in[20]; const float* n2_gb = (const float*)d_in[21];
    const float* n2_bw = (const float*)d_in[22]; const float* n2_bb = (const float*)d_in[23];
    const float* mlp_w1 = (const float*)d_in[24]; const float* mlp_b1 = (const float*)d_in[25];
    const float* mlp_w2 = (const float*)d_in[26]; const float* mlp_b2 = (const float*)d_in[27];

    float* out = (float*)d_out;                          // [B,N,D] flattened
    float* out_attn = out + (size_t)ROWS * Ddim;         // [B,H,N] flattened

    float *xn, *q, *k, *v, *ao, *mlph, *attn, *gq, *hbuf, *sc, *sh;
    cudaGetSymbolAddress((void**)&xn, g_xn);
    cudaGetSymbolAddress((void**)&q, g_q);
    cudaGetSymbolAddress((void**)&k, g_k);
    cudaGetSymbolAddress((void**)&v, g_v);
    cudaGetSymbolAddress((void**)&ao, g_ao);
    cudaGetSymbolAddress((void**)&mlph, g_mlph);
    cudaGetSymbolAddress((void**)&attn, g_attn);
    cudaGetSymbolAddress((void**)&gq, g_gq);
    cudaGetSymbolAddress((void**)&hbuf, g_h);
    cudaGetSymbolAddress((void**)&sc, g_scale);
    cudaGetSymbolAddress((void**)&sh, g_shift);

    const dim3 smallGrid(Ddim / 256, Bdim);

    // norm1 conditioning
    small_gemm_kernel<<<smallGrid, 256>>>(z, n1_hw, n1_hb, hbuf, Ddim, Ddim, 1);
    small_gemm_kernel<<<smallGrid, 256>>>(hbuf, n1_gw, n1_gb, sc, Ddim, Ddim, 0);
    small_gemm_kernel<<<smallGrid, 256>>>(hbuf, n1_bw, n1_bb, sh, Ddim, Ddim, 0);
    // x_norm1
    ln_mod_kernel<<<ROWS, 256>>>(inputs, sc, sh, xn);

    // q, k, v (TF32 tensor cores)
    dim3 g1(Ddim / 128, ROWS / 128);
    mma_gemm<0><<<g1, 256>>>(xn, wq_w, wq_b, nullptr, q, ROWS, Ddim, Ddim);
    mma_gemm<0><<<g1, 256>>>(xn, wk_w, wk_b, nullptr, k, ROWS, Ddim, Ddim);
    mma_gemm<0><<<g1, 256>>>(xn, wv_w, wv_b, nullptr, v, ROWS, Ddim, Ddim);

    // attention logits + softmax + global q
    qa_kernel<<<(ROWS * Hdim) / 8, 256>>>(q, qa_w, qa_b, attn);
    softmax_kernel<<<Bdim * Hdim, 256>>>(attn, out_attn);
    globalq_kernel<<<Bdim * Hdim, 256>>>(attn, q, gq);

    // r = gq * k * v  (into q buffer)
    r_kernel<<<(ROWS * Ddim) / 256, 256>>>(gq, k, v, q);

    // out proj + residual(inputs) -> attn_out
    mma_gemm<1><<<g1, 256>>>(q, out_w, out_b, inputs, ao, ROWS, Ddim, Ddim);

    // norm2 conditioning + x_norm2
    small_gemm_kernel<<<smallGrid, 256>>>(z, n2_hw, n2_hb, hbuf, Ddim, Ddim, 1);
    small_gemm_kernel<<<smallGrid, 256>>>(hbuf, n2_gw, n2_gb, sc, Ddim, Ddim, 0);
    small_gemm_kernel<<<smallGrid, 256>>>(hbuf, n2_bw, n2_bb, sh, Ddim, Ddim, 0);
    ln_mod_kernel<<<ROWS, 256>>>(ao, sc, sh, xn);

    // MLP (TF32 tensor cores)
    dim3 g2(MLPdim / 128, ROWS / 128);
    mma_gemm<2><<<g2, 256>>>(xn, mlp_w1, mlp_b1, nullptr, mlph, ROWS, MLPdim, Ddim);
    dim3 g3(Ddim / 128, ROWS / 128);
    mma_gemm<1><<<g3, 256>>>(mlph, mlp_w2, mlp_b2, ao, out, ROWS, Ddim, MLPdim);
}

// round 5
// speedup vs baseline: 1.1133x; 1.1133x over previous
#include <cuda_runtime.h>
#include <math.h>
#include <stdint.h>

#define Bdim 8
#define Ndim 1024
#define Ddim 1024
#define Hdim 16
#define DEPTH 64
#define MLPdim 4096
#define ROWS 8192
#define EPSLN 1e-6f
#define ISD 0.125f

__device__ float g_xn[ROWS*Ddim];
__device__ float g_q[ROWS*Ddim];
__device__ float g_k[ROWS*Ddim];
__device__ float g_v[ROWS*Ddim];
__device__ float g_ao[ROWS*Ddim];
__device__ float g_mlph[(size_t)ROWS*MLPdim];
__device__ float g_attn[Bdim*Hdim*Ndim];
__device__ float g_gq[Bdim*Hdim*DEPTH];
__device__ float g_h[Bdim*Ddim];
__device__ float g_scale[Bdim*Ddim];
__device__ float g_shift[Bdim*Ddim];
__device__ float g_wq[Ddim*Ddim];
__device__ float g_wk[Ddim*Ddim];
__device__ float g_wv[Ddim*Ddim];
__device__ float g_wo[Ddim*Ddim];
__device__ float g_w1t[(size_t)Ddim*MLPdim];
__device__ float g_w2t[(size_t)Ddim*MLPdim];

__device__ __forceinline__ uint32_t f2tf(float f){
    uint32_t u; asm("cvt.rna.tf32.f32 %0, %1;" : "=r"(u) : "f"(f)); return u;
}
__device__ __forceinline__ uint32_t cvsm(const void* p){
    uint32_t a; asm("{ .reg .u64 t; cvta.to.shared.u64 t, %1; cvt.u32.u64 %0, t; }":"=r"(a):"l"(p)); return a;
}
__device__ __forceinline__ void cp16(uint32_t d, const void* s){
    asm volatile("cp.async.cg.shared.global [%0], [%1], 16;" :: "r"(d), "l"(s));
}
__device__ __forceinline__ void mma_tf32(float* d, const uint32_t* a, const uint32_t* b){
    asm volatile(
        "mma.sync.aligned.m16n8k8.row.col.f32.tf32.tf32.f32 "
        "{%0,%1,%2,%3},{%4,%5,%6,%7},{%8,%9},{%0,%1,%2,%3};"
        : "+f"(d[0]), "+f"(d[1]), "+f"(d[2]), "+f"(d[3])
        : "r"(a[0]), "r"(a[1]), "r"(a[2]), "r"(a[3]), "r"(b[0]), "r"(b[1]));
}

// ---------------- pipelined mma.sync tf32 GEMM ----------------
// C[8192,Ntot] = epi(A[8192,Ktot] @ Wt[Ntot,Ktot]^T + bias)
// A and Wt MUST be tf32-pre-rounded. epi: 0 +b ; 1 +b+res ; 2 gelu(+b) rounded
#define SLOTF 5120        // floats per stage: A 128*20 + B 128*20
#define PIPESM (4*SLOTF*4)

__device__ __forceinline__ void load_stage(float* smbase, const float* A, const float* Wt,
    int mBase, int nBase, int Ktot, int kB, int slot, int tid){
    float* st = smbase + slot*SLOTF;
    #pragma unroll
    for(int i=0;i<2;++i){
        int idx=i*256+tid, row=idx>>2, cc=idx&3;
        cp16(cvsm(st + row*20 + cc*4), A + (size_t)(mBase+row)*Ktot + kB + cc*4);
    }
    #pragma unroll
    for(int i=0;i<2;++i){
        int idx=i*256+tid, row=idx>>2, cc=idx&3;
        cp16(cvsm(st + 2560 + row*20 + cc*4), Wt + (size_t)(nBase+row)*Ktot + kB + cc*4);
    }
}

__global__ __launch_bounds__(256,2)
void mma_gemm_pipe(const float* __restrict__ A, const float* __restrict__ Wt,
                   const float* __restrict__ bias, const float* __restrict__ res,
                   float* __restrict__ C, int Ntot, int Ktot, int epi){
    extern __shared__ float sm[];
    const int tid = threadIdx.x, lane = tid&31, warp = tid>>5;
    const int wm = warp>>2, wn = warp&3, g = lane>>2, c = lane&3;
    const int mBase = blockIdx.y*128, nBase = blockIdx.x*128;
    const int KS = Ktot/16;

    float acc[4][4][4];
    #pragma unroll
    for(int i=0;i<4;++i)
        #pragma unroll
        for(int j=0;j<4;++j)
            #pragma unroll
            for(int q=0;q<4;++q) acc[i][j][q]=0.f;

    #pragma unroll
    for(int s=0;s<3;++s){
        load_stage(sm, A, Wt, mBase, nBase, Ktot, s*16, s, tid);
        asm volatile("cp.async.commit_group;");
    }

    for(int s=0;s<KS;++s){
        __syncthreads();                       // prev compute done; slot reusable
        if(s+3<KS) load_stage(sm, A, Wt, mBase, nBase, Ktot, (s+3)*16, (s+3)&3, tid);
        asm volatile("cp.async.commit_group;");// (possibly empty) keeps count exact
        asm volatile("cp.async.wait_group 3;");
        __syncthreads();                       // stage s visible to all

        const uint32_t* as = (const uint32_t*)(sm + (s&3)*SLOTF);
        const uint32_t* bs = as + 2560;
        #pragma unroll
        for(int ks=0;ks<2;++ks){
            const int k8 = ks*8;
            uint32_t af[4][4], bf[4][2];
            #pragma unroll
            for(int i=0;i<4;++i){
                const int m = wm*64 + i*16 + g;
                af[i][0]=as[m*20+k8+c];     af[i][1]=as[(m+8)*20+k8+c];
                af[i][2]=as[m*20+k8+c+4];   af[i][3]=as[(m+8)*20+k8+c+4];
            }
            #pragma unroll
            for(int j=0;j<4;++j){
                const int n = wn*32 + j*8 + g;
                bf[j][0]=bs[n*20+k8+c];     bf[j][1]=bs[n*20+k8+c+4];
            }
            #pragma unroll
            for(int i=0;i<4;++i)
                #pragma unroll
                for(int j=0;j<4;++j)
                    mma_tf32(acc[i][j], af[i], bf[j]);
        }
    }

    #pragma unroll
    for(int i=0;i<4;++i){
        const int row0 = blockIdx.y*128 + wm*64 + i*16 + g;
        #pragma unroll
        for(int j=0;j<4;++j){
            const int col = blockIdx.x*128 + wn*32 + j*8 + 2*c;
            const float b0 = bias[col], b1 = bias[col+1];
            #pragma unroll
            for(int half=0;half<2;++half){
                const int row = row0 + half*8;
                float v0 = acc[i][j][half*2+0] + b0;
                float v1 = acc[i][j][half*2+1] + b1;
                const size_t off = (size_t)row*Ntot + col;
                if(epi==1){
                    const float2 rr = *reinterpret_cast<const float2*>(res + off);
                    v0 += rr.x; v1 += rr.y;
                } else if(epi==2){
                    v0 = 0.5f*v0*(1.f+erff(v0*0.7071067811865475f));
                    v1 = 0.5f*v1*(1.f+erff(v1*0.7071067811865475f));
                    v0 = __uint_as_float(f2tf(v0));
                    v1 = __uint_as_float(f2tf(v1));
                }
                float2 o; o.x=v0; o.y=v1;
                *reinterpret_cast<float2*>(C + off) = o;
            }
        }
    }
}

// in[K,N] -> out[N,K], RNA tf32 rounded
__global__ __launch_bounds__(256)
void tr_round(const float* __restrict__ in, float* __restrict__ out, int K, int N){
    __shared__ float t[32][33];
    const int n0 = blockIdx.x*32, k0 = blockIdx.y*32;
    #pragma unroll
    for(int i=0;i<32;i+=8)
        t[threadIdx.y+i][threadIdx.x] = in[(size_t)(k0+threadIdx.y+i)*N + n0+threadIdx.x];
    __syncthreads();
    #pragma unroll
    for(int i=0;i<32;i+=8)
        out[(size_t)(n0+threadIdx.y+i)*K + k0+threadIdx.x] =
            __uint_as_float(f2tf(t[threadIdx.x][threadIdx.y+i]));
}

__device__ __forceinline__ float bsum(float v, float* sm){
    #pragma unroll
    for(int o=16;o;o>>=1) v += __shfl_xor_sync(~0u,v,o);
    int wd=threadIdx.x>>5;
    if((threadIdx.x&31)==0) sm[wd]=v;
    __syncthreads();
    float r=0.f;
    if(threadIdx.x<8){ r=sm[threadIdx.x];
        #pragma unroll
        for(int o=4;o;o>>=1) r += __shfl_xor_sync(0xFFu,r,o);
        if(threadIdx.x==0) sm[0]=r; }
    __syncthreads(); r=sm[0]; __syncthreads(); return r;
}
__device__ __forceinline__ float bmax(float v, float* sm){
    #pragma unroll
    for(int o=16;o;o>>=1) v = fmaxf(v,__shfl_xor_sync(~0u,v,o));
    int wd=threadIdx.x>>5;
    if((threadIdx.x&31)==0) sm[wd]=v;
    __syncthreads();
    float r=-1e30f;
    if(threadIdx.x<8){ r=sm[threadIdx.x];
        #pragma unroll
        for(int o=4;o;o>>=1) r = fmaxf(r,__shfl_xor_sync(0xFFu,r,o));
        if(threadIdx.x==0) sm[0]=r; }
    __syncthreads(); r=sm[0]; __syncthreads(); return r;
}

__global__ __launch_bounds__(256)
void ln_mod(const float* __restrict__ x, const float* __restrict__ sc,
            const float* __restrict__ sh, float* __restrict__ out){
    __shared__ float sm[8];
    const int row=blockIdx.x, b=row>>10, n=row&1023;
    float4 v = reinterpret_cast<const float4*>(x+(size_t)row*Ddim)[threadIdx.x];
    float mean = bsum(v.x+v.y+v.z+v.w, sm)*(1.f/Ddim);
    float dx=v.x-mean, dy=v.y-mean, dz=v.z-mean, dw=v.w-mean;
    float var = bsum(dx*dx+dy*dy+dz*dz+dw*dw, sm)*(1.f/Ddim);
    float rs = rsqrtf(var+EPSLN);
    float s = sc[b*Ddim+n]*rs, t = sh[b*Ddim+n];
    float4 o;
    o.x=__uint_as_float(f2tf(dx*s+t)); o.y=__uint_as_float(f2tf(dy*s+t));
    o.z=__uint_as_float(f2tf(dz*s+t)); o.w=__uint_as_float(f2tf(dw*s+t));
    reinterpret_cast<float4*>(out+(size_t)row*Ddim)[threadIdx.x]=o;
}

__global__ __launch_bounds__(256)
void small_gemm(const float* __restrict__ A, const float* __restrict__ W,
                const float* __restrict__ bias, float* __restrict__ out, int act){
    const int n = blockIdx.x*256+threadIdx.x, b = blockIdx.y;
    const float* a = A+(size_t)b*Ddim;
    float acc=0.f;
    for(int k=0;k<Ddim;++k) acc = fmaf(a[k], W[(size_t)k*Ddim+n], acc);
    acc += bias[n];
    if(act) acc = fmaxf(acc,0.f);
    out[(size_t)b*Ddim+n]=acc;
}

__global__ __launch_bounds__(256)
void qa_kernel(const float* __restrict__ q, const float* __restrict__ w,
               const float* __restrict__ bias, float* __restrict__ attn){
    const int warp=threadIdx.x>>5, lane=threadIdx.x&31;
    const int gi=blockIdx.x*8+warp, hh=gi&15, bn=gi>>4;
    const float* qr = q+(size_t)bn*Ddim;
    float acc=0.f;
    #pragma unroll 4
    for(int k=lane;k<Ddim;k+=32) acc = fmaf(qr[k], w[k*Hdim+hh], acc);
    #pragma unroll
    for(int o=16;o;o>>=1) acc += __shfl_xor_sync(~0u,acc,o);
    if(lane==0){
        const int b=bn>>10, n=bn&1023;
        attn[(size_t)b*Hdim*Ndim + hh*Ndim + n] = (acc+bias[hh])*ISD;
    }
}

__global__ __launch_bounds__(256)
void softmax_kernel(float* __restrict__ attn, float* __restrict__ oa){
    __shared__ float sm[8];
    const int row=blockIdx.x;
    float4 v = reinterpret_cast<float4*>(attn+(size_t)row*Ndim)[threadIdx.x];
    float m = bmax(fmaxf(fmaxf(v.x,v.y),fmaxf(v.z,v.w)), sm);
    v.x=__expf(v.x-m); v.y=__expf(v.y-m); v.z=__expf(v.z-m); v.w=__expf(v.w-m);
    float s = bsum(v.x+v.y+v.z+v.w, sm);
    const float inv=1.f/s;
    v.x*=inv; v.y*=inv; v.z*=inv; v.w*=inv;
    reinterpret_cast<float4*>(attn+(size_t)row*Ndim)[threadIdx.x]=v;
    reinterpret_cast<float4*>(oa+(size_t)row*Ndim)[threadIdx.x]=v;
}

__global__ __launch_bounds__(256)
void globalq_kernel(const float* __restrict__ attn, const float* __restrict__ q,
                    float* __restrict__ gq){
    __shared__ float part[256];
    const int bh=blockIdx.x, b=bh>>4, hh=bh&15;
    const int g=threadIdx.x>>6, d=threadIdx.x&63;
    const float* ar = attn+(size_t)bh*Ndim;
    float acc=0.f;
    for(int n=g;n<Ndim;n+=4)
        acc = fmaf(ar[n], q[((size_t)(b*Ndim+n))*Ddim + hh*DEPTH + d], acc);
    part[threadIdx.x]=acc;
    __syncthreads();
    if(g==0) gq[(size_t)bh*DEPTH+d] = part[d]+part[64+d]+part[128+d]+part[192+d];
}

__global__ __launch_bounds__(256)
void r_kernel(const float* __restrict__ gq, const float* __restrict__ k,
              const float* __restrict__ v, float* __restrict__ r){
    const size_t i = (size_t)blockIdx.x*256+threadIdx.x;
    const int d=(int)(i&1023), b=(int)(i>>20);
    r[i] = __uint_as_float(f2tf(gq[b*Ddim+d]*k[i]*v[i]));
}

#define SYM(p,s) float* p; cudaGetSymbolAddress((void**)&p, s);

extern "C" void kernel_launch(void* const* d_in, const int* in_sizes, int n_in,
                              void* d_out, int out_size){
    const float* inputs=(const float*)d_in[0];
    const float* z=(const float*)d_in[1];
    const float *n1_hw=(const float*)d_in[2], *n1_hb=(const float*)d_in[3];
    const float *n1_gw=(const float*)d_in[4], *n1_gb=(const float*)d_in[5];
    const float *n1_bw=(const float*)d_in[6], *n1_bb=(const float*)d_in[7];
    const float *wq_w=(const float*)d_in[8],  *wq_b=(const float*)d_in[9];
    const float *wk_w=(const float*)d_in[10], *wk_b=(const float*)d_in[11];
    const float *wv_w=(const float*)d_in[12], *wv_b=(const float*)d_in[13];
    const float *qa_w=(const float*)d_in[14], *qa_b=(const float*)d_in[15];
    const float *out_w=(const float*)d_in[16],*out_b=(const float*)d_in[17];
    const float *n2_hw=(const float*)d_in[18],*n2_hb=(const float*)d_in[19];
    const float *n2_gw=(const float*)d_in[20],*n2_gb=(const float*)d_in[21];
    const float *n2_bw=(const float*)d_in[22],*n2_bb=(const float*)d_in[23];
    const float *mw1=(const float*)d_in[24],  *mb1=(const float*)d_in[25];
    const float *mw2=(const float*)d_in[26],  *mb2=(const float*)d_in[27];

    float* out=(float*)d_out;
    float* out_attn = out + (size_t)ROWS*Ddim;

    SYM(xn,g_xn) SYM(q,g_q) SYM(k,g_k) SYM(v,g_v) SYM(ao,g_ao) SYM(mlph,g_mlph)
    SYM(attn,g_attn) SYM(gq,g_gq) SYM(hbuf,g_h) SYM(sc,g_scale) SYM(sh,g_shift)
    SYM(wq,g_wq) SYM(wk,g_wk) SYM(wv,g_wv) SYM(wo,g_wo) SYM(w1t,g_w1t) SYM(w2t,g_w2t)

    cudaFuncSetAttribute(mma_gemm_pipe, cudaFuncAttributeMaxDynamicSharedMemorySize, PIPESM);

    dim3 tb(32,8);
    tr_round<<<dim3(32,32),tb>>>(wq_w, wq, Ddim, Ddim);
    tr_round<<<dim3(32,32),tb>>>(wk_w, wk, Ddim, Ddim);
    tr_round<<<dim3(32,32),tb>>>(wv_w, wv, Ddim, Ddim);
    tr_round<<<dim3(32,32),tb>>>(out_w, wo, Ddim, Ddim);
    tr_round<<<dim3(128,32),tb>>>(mw1, w1t, Ddim, MLPdim);
    tr_round<<<dim3(32,128),tb>>>(mw2, w2t, MLPdim, Ddim);

    const dim3 sg(4, Bdim);
    small_gemm<<<sg,256>>>(z, n1_hw, n1_hb, hbuf, 1);
    small_gemm<<<sg,256>>>(hbuf, n1_gw, n1_gb, sc, 0);
    small_gemm<<<sg,256>>>(hbuf, n1_bw, n1_bb, sh, 0);
    ln_mod<<<ROWS,256>>>(inputs, sc, sh, xn);

    dim3 g1(8,64);
    mma_gemm_pipe<<<g1,256,PIPESM>>>(xn, wq, wq_b, nullptr, q, Ddim, Ddim, 0);
    mma_gemm_pipe<<<g1,256,PIPESM>>>(xn, wk, wk_b, nullptr, k, Ddim, Ddim, 0);
    mma_gemm_pipe<<<g1,256,PIPESM>>>(xn, wv, wv_b, nullptr, v, Ddim, Ddim, 0);

    qa_kernel<<<ROWS*Hdim/8,256>>>(q, qa_w, qa_b, attn);
    softmax_kernel<<<Bdim*Hdim,256>>>(attn, out_attn);
    globalq_kernel<<<Bdim*Hdim,256>>>(attn, q, gq);
    r_kernel<<<(size_t)ROWS*Ddim/256,256>>>(gq, k, v, q);

    mma_gemm_pipe<<<g1,256,PIPESM>>>(q, wo, out_b, inputs, ao, Ddim, Ddim, 1);

    small_gemm<<<sg,256>>>(z, n2_hw, n2_hb, hbuf, 1);
    small_gemm<<<sg,256>>>(hbuf, n2_gw, n2_gb, sc, 0);
    small_gemm<<<sg,256>>>(hbuf, n2_bw, n2_bb, sh, 0);
    ln_mod<<<ROWS,256>>>(ao, sc, sh, xn);

    dim3 g2(32,64);
    mma_gemm_pipe<<<g2,256,PIPESM>>>(xn, w1t, mb1, nullptr, mlph, MLPdim, Ddim, 2);
    dim3 g3(8,64);
    mma_gemm_pipe<<<g3,256,PIPESM>>>(mlph, w2t, mb2, ao, out, Ddim, MLPdim, 1);
}

// round 6
// speedup vs baseline: 1.1509x; 1.0338x over previous
#include <cuda_runtime.h>
#include <math.h>
#include <stdint.h>

#define Bdim 8
#define Ndim 1024
#define Ddim 1024
#define Hdim 16
#define DEPTH 64
#define MLPdim 4096
#define ROWS 8192
#define EPSLN 1e-6f
#define ISD 0.125f

__device__ float g_xn[ROWS*Ddim];
__device__ float g_q[ROWS*Ddim];
__device__ float g_k[ROWS*Ddim];
__device__ float g_v[ROWS*Ddim];
__device__ float g_ao[ROWS*Ddim];
__device__ float g_mlph[(size_t)ROWS*MLPdim];
__device__ float g_attn[Bdim*Hdim*Ndim];
__device__ float g_gq[Bdim*Hdim*DEPTH];
__device__ float g_h[Bdim*Ddim];
__device__ float g_scale[Bdim*Ddim];
__device__ float g_shift[Bdim*Ddim];
__device__ float g_wq[Ddim*Ddim];
__device__ float g_wk[Ddim*Ddim];
__device__ float g_wv[Ddim*Ddim];
__device__ float g_wo[Ddim*Ddim];
__device__ float g_w1t[(size_t)Ddim*MLPdim];
__device__ float g_w2t[(size_t)Ddim*MLPdim];

__device__ __forceinline__ uint32_t f2tf(float f){
    uint32_t u; asm("cvt.rna.tf32.f32 %0, %1;" : "=r"(u) : "f"(f)); return u;
}
__device__ __forceinline__ uint32_t cvsm(const void* p){
    uint32_t a; asm("{ .reg .u64 t; cvta.to.shared.u64 t, %1; cvt.u32.u64 %0, t; }":"=r"(a):"l"(p)); return a;
}
__device__ __forceinline__ void cp16(uint32_t d, const void* s){
    asm volatile("cp.async.cg.shared.global [%0], [%1], 16;" :: "r"(d), "l"(s));
}
__device__ __forceinline__ void ldsm4(uint32_t* r, uint32_t a){
    asm volatile("ldmatrix.sync.aligned.m8n8.x4.shared.b16 {%0,%1,%2,%3},[%4];"
        : "=r"(r[0]),"=r"(r[1]),"=r"(r[2]),"=r"(r[3]) : "r"(a));
}
__device__ __forceinline__ void mma_tf32(float* d, const uint32_t* a, const uint32_t* b){
    asm volatile(
        "mma.sync.aligned.m16n8k8.row.col.f32.tf32.tf32.f32 "
        "{%0,%1,%2,%3},{%4,%5,%6,%7},{%8,%9},{%0,%1,%2,%3};"
        : "+f"(d[0]), "+f"(d[1]), "+f"(d[2]), "+f"(d[3])
        : "r"(a[0]), "r"(a[1]), "r"(a[2]), "r"(a[3]), "r"(b[0]), "r"(b[1]));
}

// ---------------- pipelined mma.sync tf32 GEMM (ldmatrix, no spills) ----------------
// C[8192,Ntot] = epi(A[8192,Ktot] @ Wt[Ntot,Ktot]^T + bias); inputs tf32-pre-rounded
#define SLOTF 5120
#define PIPESM (4*SLOTF*4)

__device__ __forceinline__ void load_stage(float* smbase, const float* A, const float* Wt,
    int mBase, int nBase, int Ktot, int kB, int slot, int tid){
    float* st = smbase + slot*SLOTF;
    #pragma unroll
    for(int i=0;i<2;++i){
        int idx=i*256+tid, row=idx>>2, cc=idx&3;
        cp16(cvsm(st + row*20 + cc*4), A + (size_t)(mBase+row)*Ktot + kB + cc*4);
    }
    #pragma unroll
    for(int i=0;i<2;++i){
        int idx=i*256+tid, row=idx>>2, cc=idx&3;
        cp16(cvsm(st + 2560 + row*20 + cc*4), Wt + (size_t)(nBase+row)*Ktot + kB + cc*4);
    }
}

__global__ __launch_bounds__(256)
void mma_gemm_pipe(const float* __restrict__ A, const float* __restrict__ Wt,
                   const float* __restrict__ bias, const float* __restrict__ res,
                   float* __restrict__ C, int Ntot, int Ktot, int epi){
    extern __shared__ float sm[];
    const int tid = threadIdx.x, lane = tid&31, warp = tid>>5;
    const int wm = warp>>2, wn = warp&3, g = lane>>2, c = lane&3;
    const int mBase = blockIdx.y*128, nBase = blockIdx.x*128;
    const int KS = Ktot/16;
    const uint32_t smb = cvsm(sm);

    // per-thread ldmatrix offsets (bytes)
    const uint32_t aoff = ((wm*64 + (lane&7) + ((lane>>3)&1)*8)*20 + ((lane>>4)&1)*4)*4;
    const uint32_t boff = (2560 + (wn*32 + (lane&7) + ((lane>>4)&1)*8)*20 + ((lane>>3)&1)*4)*4;

    float acc[4][4][4];
    #pragma unroll
    for(int i=0;i<4;++i)
        #pragma unroll
        for(int j=0;j<4;++j)
            #pragma unroll
            for(int q=0;q<4;++q) acc[i][j][q]=0.f;

    #pragma unroll
    for(int s=0;s<3;++s){
        load_stage(sm, A, Wt, mBase, nBase, Ktot, s*16, s, tid);
        asm volatile("cp.async.commit_group;");
    }

    for(int s=0;s<KS;++s){
        __syncthreads();
        if(s+3<KS) load_stage(sm, A, Wt, mBase, nBase, Ktot, (s+3)*16, (s+3)&3, tid);
        asm volatile("cp.async.commit_group;");
        asm volatile("cp.async.wait_group 3;");
        __syncthreads();

        const uint32_t sa = smb + (uint32_t)(s&3)*SLOTF*4;
        #pragma unroll
        for(int ks=0;ks<2;++ks){
            const uint32_t k8b = (uint32_t)(ks*8)*4;
            uint32_t af[4][4], bf[4][2], bt[4];
            #pragma unroll
            for(int i=0;i<4;++i) ldsm4(af[i], sa + aoff + i*16*20*4 + k8b);
            ldsm4(bt, sa + boff + k8b);
            bf[0][0]=bt[0]; bf[0][1]=bt[1]; bf[1][0]=bt[2]; bf[1][1]=bt[3];
            ldsm4(bt, sa + boff + 16*20*4 + k8b);
            bf[2][0]=bt[0]; bf[2][1]=bt[1]; bf[3][0]=bt[2]; bf[3][1]=bt[3];
            #pragma unroll
            for(int i=0;i<4;++i)
                #pragma unroll
                for(int j=0;j<4;++j)
                    mma_tf32(acc[i][j], af[i], bf[j]);
        }
    }

    #pragma unroll
    for(int i=0;i<4;++i){
        const int row0 = mBase + wm*64 + i*16 + g;
        #pragma unroll
        for(int j=0;j<4;++j){
            const int col = nBase + wn*32 + j*8 + 2*c;
            const float b0 = bias[col], b1 = bias[col+1];
            #pragma unroll
            for(int half=0;half<2;++half){
                const int row = row0 + half*8;
                float v0 = acc[i][j][half*2+0] + b0;
                float v1 = acc[i][j][half*2+1] + b1;
                const size_t off = (size_t)row*Ntot + col;
                if(epi==1){
                    const float2 rr = *reinterpret_cast<const float2*>(res + off);
                    v0 += rr.x; v1 += rr.y;
                } else if(epi==2){
                    v0 = 0.5f*v0*(1.f+erff(v0*0.7071067811865475f));
                    v1 = 0.5f*v1*(1.f+erff(v1*0.7071067811865475f));
                    v0 = __uint_as_float(f2tf(v0));
                    v1 = __uint_as_float(f2tf(v1));
                }
                float2 o; o.x=v0; o.y=v1;
                *reinterpret_cast<float2*>(C + off) = o;
            }
        }
    }
}

// in[K,N] -> out[N,K], RNA tf32 rounded
__global__ __launch_bounds__(256)
void tr_round(const float* __restrict__ in, float* __restrict__ out, int K, int N){
    __shared__ float t[32][33];
    const int n0 = blockIdx.x*32, k0 = blockIdx.y*32;
    #pragma unroll
    for(int i=0;i<32;i+=8)
        t[threadIdx.y+i][threadIdx.x] = in[(size_t)(k0+threadIdx.y+i)*N + n0+threadIdx.x];
    __syncthreads();
    #pragma unroll
    for(int i=0;i<32;i+=8)
        out[(size_t)(n0+threadIdx.y+i)*K + k0+threadIdx.x] =
            __uint_as_float(f2tf(t[threadIdx.x][threadIdx.y+i]));
}

__device__ __forceinline__ float bsum(float v, float* sm){
    #pragma unroll
    for(int o=16;o;o>>=1) v += __shfl_xor_sync(~0u,v,o);
    int wd=threadIdx.x>>5;
    if((threadIdx.x&31)==0) sm[wd]=v;
    __syncthreads();
    float r=0.f;
    if(threadIdx.x<8){ r=sm[threadIdx.x];
        #pragma unroll
        for(int o=4;o;o>>=1) r += __shfl_xor_sync(0xFFu,r,o);
        if(threadIdx.x==0) sm[0]=r; }
    __syncthreads(); r=sm[0]; __syncthreads(); return r;
}
__device__ __forceinline__ float bmax(float v, float* sm){
    #pragma unroll
    for(int o=16;o;o>>=1) v = fmaxf(v,__shfl_xor_sync(~0u,v,o));
    int wd=threadIdx.x>>5;
    if((threadIdx.x&31)==0) sm[wd]=v;
    __syncthreads();
    float r=-1e30f;
    if(threadIdx.x<8){ r=sm[threadIdx.x];
        #pragma unroll
        for(int o=4;o;o>>=1) r = fmaxf(r,__shfl_xor_sync(0xFFu,r,o));
        if(threadIdx.x==0) sm[0]=r; }
    __syncthreads(); r=sm[0]; __syncthreads(); return r;
}

__global__ __launch_bounds__(256)
void ln_mod(const float* __restrict__ x, const float* __restrict__ sc,
            const float* __restrict__ sh, float* __restrict__ out){
    __shared__ float sm[8];
    const int row=blockIdx.x, b=row>>10, n=row&1023;
    float4 v = reinterpret_cast<const float4*>(x+(size_t)row*Ddim)[threadIdx.x];
    float mean = bsum(v.x+v.y+v.z+v.w, sm)*(1.f/Ddim);
    float dx=v.x-mean, dy=v.y-mean, dz=v.z-mean, dw=v.w-mean;
    float var = bsum(dx*dx+dy*dy+dz*dz+dw*dw, sm)*(1.f/Ddim);
    float rs = rsqrtf(var+EPSLN);
    float s = sc[b*Ddim+n]*rs, t = sh[b*Ddim+n];
    float4 o;
    o.x=__uint_as_float(f2tf(dx*s+t)); o.y=__uint_as_float(f2tf(dy*s+t));
    o.z=__uint_as_float(f2tf(dz*s+t)); o.w=__uint_as_float(f2tf(dw*s+t));
    reinterpret_cast<float4*>(out+(size_t)row*Ddim)[threadIdx.x]=o;
}

__global__ __launch_bounds__(256)
void small_gemm(const float* __restrict__ A, const float* __restrict__ W,
                const float* __restrict__ bias, float* __restrict__ out, int act){
    const int n = blockIdx.x*256+threadIdx.x, b = blockIdx.y;
    const float* a = A+(size_t)b*Ddim;
    float acc=0.f;
    for(int k=0;k<Ddim;++k) acc = fmaf(a[k], W[(size_t)k*Ddim+n], acc);
    acc += bias[n];
    if(act) acc = fmaxf(acc,0.f);
    out[(size_t)b*Ddim+n]=acc;
}

__global__ __launch_bounds__(256)
void qa_kernel(const float* __restrict__ q, const float* __restrict__ w,
               const float* __restrict__ bias, float* __restrict__ attn){
    const int warp=threadIdx.x>>5, lane=threadIdx.x&31;
    const int gi=blockIdx.x*8+warp, hh=gi&15, bn=gi>>4;
    const float* qr = q+(size_t)bn*Ddim;
    float acc=0.f;
    #pragma unroll 4
    for(int k=lane;k<Ddim;k+=32) acc = fmaf(qr[k], w[k*Hdim+hh], acc);
    #pragma unroll
    for(int o=16;o;o>>=1) acc += __shfl_xor_sync(~0u,acc,o);
    if(lane==0){
        const int b=bn>>10, n=bn&1023;
        attn[(size_t)b*Hdim*Ndim + hh*Ndim + n] = (acc+bias[hh])*ISD;
    }
}

__global__ __launch_bounds__(256)
void softmax_kernel(float* __restrict__ attn, float* __restrict__ oa){
    __shared__ float sm[8];
    const int row=blockIdx.x;
    float4 v = reinterpret_cast<float4*>(attn+(size_t)row*Ndim)[threadIdx.x];
    float m = bmax(fmaxf(fmaxf(v.x,v.y),fmaxf(v.z,v.w)), sm);
    v.x=__expf(v.x-m); v.y=__expf(v.y-m); v.z=__expf(v.z-m); v.w=__expf(v.w-m);
    float s = bsum(v.x+v.y+v.z+v.w, sm);
    const float inv=1.f/s;
    v.x*=inv; v.y*=inv; v.z*=inv; v.w*=inv;
    reinterpret_cast<float4*>(attn+(size_t)row*Ndim)[threadIdx.x]=v;
    reinterpret_cast<float4*>(oa+(size_t)row*Ndim)[threadIdx.x]=v;
}

__global__ __launch_bounds__(256)
void globalq_kernel(const float* __restrict__ attn, const float* __restrict__ q,
                    float* __restrict__ gq){
    __shared__ float part[256];
    const int bh=blockIdx.x, b=bh>>4, hh=bh&15;
    const int g=threadIdx.x>>6, d=threadIdx.x&63;
    const float* ar = attn+(size_t)bh*Ndim;
    float acc=0.f;
    for(int n=g;n<Ndim;n+=4)
        acc = fmaf(ar[n], q[((size_t)(b*Ndim+n))*Ddim + hh*DEPTH + d], acc);
    part[threadIdx.x]=acc;
    __syncthreads();
    if(g==0) gq[(size_t)bh*DEPTH+d] = part[d]+part[64+d]+part[128+d]+part[192+d];
}

__global__ __launch_bounds__(256)
void r_kernel(const float* __restrict__ gq, const float* __restrict__ k,
              const float* __restrict__ v, float* __restrict__ r){
    const size_t i = (size_t)blockIdx.x*256+threadIdx.x;
    const int d=(int)(i&1023), b=(int)(i>>20);
    r[i] = __uint_as_float(f2tf(gq[b*Ddim+d]*k[i]*v[i]));
}

#define SYM(p,s) float* p; cudaGetSymbolAddress((void**)&p, s);

extern "C" void kernel_launch(void* const* d_in, const int* in_sizes, int n_in,
                              void* d_out, int out_size){
    const float* inputs=(const float*)d_in[0];
    const float* z=(const float*)d_in[1];
    const float *n1_hw=(const float*)d_in[2], *n1_hb=(const float*)d_in[3];
    const float *n1_gw=(const float*)d_in[4], *n1_gb=(const float*)d_in[5];
    const float *n1_bw=(const float*)d_in[6], *n1_bb=(const float*)d_in[7];
    const float *wq_w=(const float*)d_in[8],  *wq_b=(const float*)d_in[9];
    const float *wk_w=(const float*)d_in[10], *wk_b=(const float*)d_in[11];
    const float *wv_w=(const float*)d_in[12], *wv_b=(const float*)d_in[13];
    const float *qa_w=(const float*)d_in[14], *qa_b=(const float*)d_in[15];
    const float *out_w=(const float*)d_in[16],*out_b=(const float*)d_in[17];
    const float *n2_hw=(const float*)d_in[18],*n2_hb=(const float*)d_in[19];
    const float *n2_gw=(const float*)d_in[20],*n2_gb=(const float*)d_in[21];
    const float *n2_bw=(const float*)d_in[22],*n2_bb=(const float*)d_in[23];
    const float *mw1=(const float*)d_in[24],  *mb1=(const float*)d_in[25];
    const float *mw2=(const float*)d_in[26],  *mb2=(const float*)d_in[27];

    float* out=(float*)d_out;
    float* out_attn = out + (size_t)ROWS*Ddim;

    SYM(xn,g_xn) SYM(q,g_q) SYM(k,g_k) SYM(v,g_v) SYM(ao,g_ao) SYM(mlph,g_mlph)
    SYM(attn,g_attn) SYM(gq,g_gq) SYM(hbuf,g_h) SYM(sc,g_scale) SYM(sh,g_shift)
    SYM(wq,g_wq) SYM(wk,g_wk) SYM(wv,g_wv) SYM(wo,g_wo) SYM(w1t,g_w1t) SYM(w2t,g_w2t)

    cudaFuncSetAttribute(mma_gemm_pipe, cudaFuncAttributeMaxDynamicSharedMemorySize, PIPESM);

    dim3 tb(32,8);
    tr_round<<<dim3(32,32),tb>>>(wq_w, wq, Ddim, Ddim);
    tr_round<<<dim3(32,32),tb>>>(wk_w, wk, Ddim, Ddim);
    tr_round<<<dim3(32,32),tb>>>(wv_w, wv, Ddim, Ddim);
    tr_round<<<dim3(32,32),tb>>>(out_w, wo, Ddim, Ddim);
    tr_round<<<dim3(128,32),tb>>>(mw1, w1t, Ddim, MLPdim);
    tr_round<<<dim3(32,128),tb>>>(mw2, w2t, MLPdim, Ddim);

    const dim3 sg(4, Bdim);
    small_gemm<<<sg,256>>>(z, n1_hw, n1_hb, hbuf, 1);
    small_gemm<<<sg,256>>>(hbuf, n1_gw, n1_gb, sc, 0);
    small_gemm<<<sg,256>>>(hbuf, n1_bw, n1_bb, sh, 0);
    ln_mod<<<ROWS,256>>>(inputs, sc, sh, xn);

    dim3 g1(8,64);
    mma_gemm_pipe<<<g1,256,PIPESM>>>(xn, wq, wq_b, nullptr, q, Ddim, Ddim, 0);
    mma_gemm_pipe<<<g1,256,PIPESM>>>(xn, wk, wk_b, nullptr, k, Ddim, Ddim, 0);
    mma_gemm_pipe<<<g1,256,PIPESM>>>(xn, wv, wv_b, nullptr, v, Ddim, Ddim, 0);

    qa_kernel<<<ROWS*Hdim/8,256>>>(q, qa_w, qa_b, attn);
    softmax_kernel<<<Bdim*Hdim,256>>>(attn, out_attn);
    globalq_kernel<<<Bdim*Hdim,256>>>(attn, q, gq);
    r_kernel<<<(size_t)ROWS*Ddim/256,256>>>(gq, k, v, q);

    mma_gemm_pipe<<<g1,256,PIPESM>>>(q, wo, out_b, inputs, ao, Ddim, Ddim, 1);

    small_gemm<<<sg,256>>>(z, n2_hw, n2_hb, hbuf, 1);
    small_gemm<<<sg,256>>>(hbuf, n2_gw, n2_gb, sc, 0);
    small_gemm<<<sg,256>>>(hbuf, n2_bw, n2_bb, sh, 0);
    ln_mod<<<ROWS,256>>>(ao, sc, sh, xn);

    dim3 g2(32,64);
    mma_gemm_pipe<<<g2,256,PIPESM>>>(xn, w1t, mb1, nullptr, mlph, MLPdim, Ddim, 2);
    dim3 g3(8,64);
    mma_gemm_pipe<<<g3,256,PIPESM>>>(mlph, w2t, mb2, ao, out, Ddim, MLPdim, 1);
}

// round 7
// speedup vs baseline: 1.1621x; 1.0097x over previous
#include <cuda_runtime.h>
#include <math.h>
#include <stdint.h>

#define Bdim 8
#define Ndim 1024
#define Ddim 1024
#define Hdim 16
#define DEPTH 64
#define MLPdim 4096
#define ROWS 8192
#define EPSLN 1e-6f
#define ISD 0.125f

__device__ float g_xn[ROWS*Ddim];
__device__ float g_q[ROWS*Ddim];
__device__ float g_k[ROWS*Ddim];
__device__ float g_v[ROWS*Ddim];
__device__ float g_ao[ROWS*Ddim];
__device__ float g_mlph[(size_t)ROWS*MLPdim];
__device__ float g_attn[Bdim*Hdim*Ndim];
__device__ float g_gq[Bdim*Hdim*DEPTH];
__device__ float g_h[Bdim*Ddim];
__device__ float g_scale[Bdim*Ddim];
__device__ float g_shift[Bdim*Ddim];
__device__ float g_wq[Ddim*Ddim];
__device__ float g_wk[Ddim*Ddim];
__device__ float g_wv[Ddim*Ddim];
__device__ float g_wo[Ddim*Ddim];
__device__ float g_w1t[(size_t)Ddim*MLPdim];
__device__ float g_w2t[(size_t)Ddim*MLPdim];

__device__ __forceinline__ uint32_t f2tf(float f){
    uint32_t u; asm("cvt.rna.tf32.f32 %0, %1;" : "=r"(u) : "f"(f)); return u;
}
__device__ __forceinline__ uint32_t cvsm(const void* p){
    uint32_t a; asm("{ .reg .u64 t; cvta.to.shared.u64 t, %1; cvt.u32.u64 %0, t; }":"=r"(a):"l"(p)); return a;
}
__device__ __forceinline__ void cp16(uint32_t d, const void* s){
    asm volatile("cp.async.cg.shared.global [%0], [%1], 16;" :: "r"(d), "l"(s));
}
__device__ __forceinline__ void ldsm4(uint32_t* r, uint32_t a){
    asm volatile("ldmatrix.sync.aligned.m8n8.x4.shared.b16 {%0,%1,%2,%3},[%4];"
        : "=r"(r[0]),"=r"(r[1]),"=r"(r[2]),"=r"(r[3]) : "r"(a));
}
__device__ __forceinline__ void mma_tf32(float* d, const uint32_t* a, const uint32_t* b){
    asm volatile(
        "mma.sync.aligned.m16n8k8.row.col.f32.tf32.tf32.f32 "
        "{%0,%1,%2,%3},{%4,%5,%6,%7},{%8,%9},{%0,%1,%2,%3};"
        : "+f"(d[0]), "+f"(d[1]), "+f"(d[2]), "+f"(d[3])
        : "r"(a[0]), "r"(a[1]), "r"(a[2]), "r"(a[3]), "r"(b[0]), "r"(b[1]));
}

// ---------------- pipelined mma.sync tf32 GEMM, 3-stage, 2 CTA/SM ----------------
#define SLOTF 5120
#define PIPESM (3*SLOTF*4)

__device__ __forceinline__ void load_stage(float* smbase, const float* A, const float* Wt,
    int mBase, int nBase, int Ktot, int kB, int slot, int tid){
    float* st = smbase + slot*SLOTF;
    #pragma unroll
    for(int i=0;i<2;++i){
        int idx=i*256+tid, row=idx>>2, cc=idx&3;
        cp16(cvsm(st + row*20 + cc*4), A + (size_t)(mBase+row)*Ktot + kB + cc*4);
    }
    #pragma unroll
    for(int i=0;i<2;++i){
        int idx=i*256+tid, row=idx>>2, cc=idx&3;
        cp16(cvsm(st + 2560 + row*20 + cc*4), Wt + (size_t)(nBase+row)*Ktot + kB + cc*4);
    }
}

__global__ __launch_bounds__(256,2)
void mma_gemm_pipe(const float* __restrict__ A, const float* __restrict__ Wt,
                   const float* __restrict__ bias, const float* __restrict__ res,
                   float* __restrict__ C, int Ntot, int Ktot, int epi){
    extern __shared__ float sm[];
    const int tid = threadIdx.x, lane = tid&31, warp = tid>>5;
    const int wm = warp>>2, wn = warp&3, g = lane>>2, c = lane&3;
    const int mBase = blockIdx.y*128, nBase = blockIdx.x*128;
    const int KS = Ktot/16;
    const uint32_t smb = cvsm(sm);

    const uint32_t aoff = ((wm*64 + (lane&7) + ((lane>>3)&1)*8)*20 + ((lane>>4)&1)*4)*4;
    const uint32_t boff = (2560 + (wn*32 + (lane&7) + ((lane>>4)&1)*8)*20 + ((lane>>3)&1)*4)*4;

    float acc[4][4][4];
    #pragma unroll
    for(int i=0;i<4;++i)
        #pragma unroll
        for(int j=0;j<4;++j)
            #pragma unroll
            for(int q=0;q<4;++q) acc[i][j][q]=0.f;

    #pragma unroll
    for(int s=0;s<2;++s){
        load_stage(sm, A, Wt, mBase, nBase, Ktot, s*16, s, tid);
        asm volatile("cp.async.commit_group;");
    }

    int slot = 0;
    for(int s=0;s<KS;++s){
        if(s+2<KS){
            int ld = slot+2; if(ld>=3) ld-=3;
            load_stage(sm, A, Wt, mBase, nBase, Ktot, (s+2)*16, ld, tid);
        }
        asm volatile("cp.async.commit_group;");
        asm volatile("cp.async.wait_group 2;");
        __syncthreads();

        const uint32_t sa = smb + (uint32_t)slot*SLOTF*4;
        #pragma unroll
        for(int ks=0;ks<2;++ks){
            const uint32_t k8b = (uint32_t)(ks*8)*4;
            uint32_t af[4][4], bf[4][2], bt[4];
            #pragma unroll
            for(int i=0;i<4;++i) ldsm4(af[i], sa + aoff + i*16*20*4 + k8b);
            ldsm4(bt, sa + boff + k8b);
            bf[0][0]=bt[0]; bf[0][1]=bt[1]; bf[1][0]=bt[2]; bf[1][1]=bt[3];
            ldsm4(bt, sa + boff + 16*20*4 + k8b);
            bf[2][0]=bt[0]; bf[2][1]=bt[1]; bf[3][0]=bt[2]; bf[3][1]=bt[3];
            #pragma unroll
            for(int i=0;i<4;++i)
                #pragma unroll
                for(int j=0;j<4;++j)
                    mma_tf32(acc[i][j], af[i], bf[j]);
        }
        __syncthreads();
        if(++slot==3) slot=0;
    }

    #pragma unroll
    for(int i=0;i<4;++i){
        const int row0 = mBase + wm*64 + i*16 + g;
        #pragma unroll
        for(int j=0;j<4;++j){
            const int col = nBase + wn*32 + j*8 + 2*c;
            const float b0 = bias[col], b1 = bias[col+1];
            #pragma unroll
            for(int half=0;half<2;++half){
                const int row = row0 + half*8;
                float v0 = acc[i][j][half*2+0] + b0;
                float v1 = acc[i][j][half*2+1] + b1;
                const size_t off = (size_t)row*Ntot + col;
                if(epi==1){
                    const float2 rr = *reinterpret_cast<const float2*>(res + off);
                    v0 += rr.x; v1 += rr.y;
                } else if(epi==2){
                    v0 = 0.5f*v0*(1.f+erff(v0*0.7071067811865475f));
                    v1 = 0.5f*v1*(1.f+erff(v1*0.7071067811865475f));
                    v0 = __uint_as_float(f2tf(v0));
                    v1 = __uint_as_float(f2tf(v1));
                }
                float2 o; o.x=v0; o.y=v1;
                *reinterpret_cast<float2*>(C + off) = o;
            }
        }
    }
}

__global__ __launch_bounds__(256)
void tr_round(const float* __restrict__ in, float* __restrict__ out, int K, int N){
    __shared__ float t[32][33];
    const int n0 = blockIdx.x*32, k0 = blockIdx.y*32;
    #pragma unroll
    for(int i=0;i<32;i+=8)
        t[threadIdx.y+i][threadIdx.x] = in[(size_t)(k0+threadIdx.y+i)*N + n0+threadIdx.x];
    __syncthreads();
    #pragma unroll
    for(int i=0;i<32;i+=8)
        out[(size_t)(n0+threadIdx.y+i)*K + k0+threadIdx.x] =
            __uint_as_float(f2tf(t[threadIdx.x][threadIdx.y+i]));
}

__device__ __forceinline__ float bsum(float v, float* sm){
    #pragma unroll
    for(int o=16;o;o>>=1) v += __shfl_xor_sync(~0u,v,o);
    int wd=threadIdx.x>>5;
    if((threadIdx.x&31)==0) sm[wd]=v;
    __syncthreads();
    float r=0.f;
    if(threadIdx.x<8){ r=sm[threadIdx.x];
        #pragma unroll
        for(int o=4;o;o>>=1) r += __shfl_xor_sync(0xFFu,r,o);
        if(threadIdx.x==0) sm[0]=r; }
    __syncthreads(); r=sm[0]; __syncthreads(); return r;
}
__device__ __forceinline__ float bmax(float v, float* sm){
    #pragma unroll
    for(int o=16;o;o>>=1) v = fmaxf(v,__shfl_xor_sync(~0u,v,o));
    int wd=threadIdx.x>>5;
    if((threadIdx.x&31)==0) sm[wd]=v;
    __syncthreads();
    float r=-1e30f;
    if(threadIdx.x<8){ r=sm[threadIdx.x];
        #pragma unroll
        for(int o=4;o;o>>=1) r = fmaxf(r,__shfl_xor_sync(0xFFu,r,o));
        if(threadIdx.x==0) sm[0]=r; }
    __syncthreads(); r=sm[0]; __syncthreads(); return r;
}

__global__ __launch_bounds__(256)
void ln_mod(const float* __restrict__ x, const float* __restrict__ sc,
            const float* __restrict__ sh, float* __restrict__ out){
    __shared__ float sm[8];
    const int row=blockIdx.x, b=row>>10, n=row&1023;
    float4 v = reinterpret_cast<const float4*>(x+(size_t)row*Ddim)[threadIdx.x];
    float mean = bsum(v.x+v.y+v.z+v.w, sm)*(1.f/Ddim);
    float dx=v.x-mean, dy=v.y-mean, dz=v.z-mean, dw=v.w-mean;
    float var = bsum(dx*dx+dy*dy+dz*dz+dw*dw, sm)*(1.f/Ddim);
    float rs = rsqrtf(var+EPSLN);
    float s = sc[b*Ddim+n]*rs, t = sh[b*Ddim+n];
    float4 o;
    o.x=__uint_as_float(f2tf(dx*s+t)); o.y=__uint_as_float(f2tf(dy*s+t));
    o.z=__uint_as_float(f2tf(dz*s+t)); o.w=__uint_as_float(f2tf(dw*s+t));
    reinterpret_cast<float4*>(out+(size_t)row*Ddim)[threadIdx.x]=o;
}

__global__ __launch_bounds__(256)
void small_gemm(const float* __restrict__ A, const float* __restrict__ W,
                const float* __restrict__ bias, float* __restrict__ out, int act){
    const int n = blockIdx.x*256+threadIdx.x, b = blockIdx.y;
    const float* a = A+(size_t)b*Ddim;
    float acc=0.f;
    for(int k=0;k<Ddim;++k) acc = fmaf(a[k], W[(size_t)k*Ddim+n], acc);
    acc += bias[n];
    if(act) acc = fmaxf(acc,0.f);
    out[(size_t)b*Ddim+n]=acc;
}

__global__ __launch_bounds__(256)
void qa_kernel(const float* __restrict__ q, const float* __restrict__ w,
               const float* __restrict__ bias, float* __restrict__ attn){
    const int warp=threadIdx.x>>5, lane=threadIdx.x&31;
    const int gi=blockIdx.x*8+warp, hh=gi&15, bn=gi>>4;
    const float* qr = q+(size_t)bn*Ddim;
    float acc=0.f;
    #pragma unroll 4
    for(int k=lane;k<Ddim;k+=32) acc = fmaf(qr[k], w[k*Hdim+hh], acc);
    #pragma unroll
    for(int o=16;o;o>>=1) acc += __shfl_xor_sync(~0u,acc,o);
    if(lane==0){
        const int b=bn>>10, n=bn&1023;
        attn[(size_t)b*Hdim*Ndim + hh*Ndim + n] = (acc+bias[hh])*ISD;
    }
}

__global__ __launch_bounds__(256)
void softmax_kernel(float* __restrict__ attn, float* __restrict__ oa){
    __shared__ float sm[8];
    const int row=blockIdx.x;
    float4 v = reinterpret_cast<float4*>(attn+(size_t)row*Ndim)[threadIdx.x];
    float m = bmax(fmaxf(fmaxf(v.x,v.y),fmaxf(v.z,v.w)), sm);
    v.x=__expf(v.x-m); v.y=__expf(v.y-m); v.z=__expf(v.z-m); v.w=__expf(v.w-m);
    float s = bsum(v.x+v.y+v.z+v.w, sm);
    const float inv=1.f/s;
    v.x*=inv; v.y*=inv; v.z*=inv; v.w*=inv;
    reinterpret_cast<float4*>(attn+(size_t)row*Ndim)[threadIdx.x]=v;
    reinterpret_cast<float4*>(oa+(size_t)row*Ndim)[threadIdx.x]=v;
}

__global__ __launch_bounds__(256)
void globalq_kernel(const float* __restrict__ attn, const float* __restrict__ q,
                    float* __restrict__ gq){
    __shared__ float part[256];
    const int bh=blockIdx.x, b=bh>>4, hh=bh&15;
    const int g=threadIdx.x>>6, d=threadIdx.x&63;
    const float* ar = attn+(size_t)bh*Ndim;
    float acc=0.f;
    for(int n=g;n<Ndim;n+=4)
        acc = fmaf(ar[n], q[((size_t)(b*Ndim+n))*Ddim + hh*DEPTH + d], acc);
    part[threadIdx.x]=acc;
    __syncthreads();
    if(g==0) gq[(size_t)bh*DEPTH+d] = part[d]+part[64+d]+part[128+d]+part[192+d];
}

__global__ __launch_bounds__(256)
void r_kernel(const float* __restrict__ gq, const float* __restrict__ k,
              const float* __restrict__ v, float* __restrict__ r){
    const size_t i = (size_t)blockIdx.x*256+threadIdx.x;
    const int d=(int)(i&1023), b=(int)(i>>20);
    r[i] = __uint_as_float(f2tf(gq[b*Ddim+d]*k[i]*v[i]));
}

#define SYM(p,s) float* p; cudaGetSymbolAddress((void**)&p, s);

extern "C" void kernel_launch(void* const* d_in, const int* in_sizes, int n_in,
                              void* d_out, int out_size){
    const float* inputs=(const float*)d_in[0];
    const float* z=(const float*)d_in[1];
    const float *n1_hw=(const float*)d_in[2], *n1_hb=(const float*)d_in[3];
    const float *n1_gw=(const float*)d_in[4], *n1_gb=(const float*)d_in[5];
    const float *n1_bw=(const float*)d_in[6], *n1_bb=(const float*)d_in[7];
    const float *wq_w=(const float*)d_in[8],  *wq_b=(const float*)d_in[9];
    const float *wk_w=(const float*)d_in[10], *wk_b=(const float*)d_in[11];
    const float *wv_w=(const float*)d_in[12], *wv_b=(const float*)d_in[13];
    const float *qa_w=(const float*)d_in[14], *qa_b=(const float*)d_in[15];
    const float *out_w=(const float*)d_in[16],*out_b=(const float*)d_in[17];
    const float *n2_hw=(const float*)d_in[18],*n2_hb=(const float*)d_in[19];
    const float *n2_gw=(const float*)d_in[20],*n2_gb=(const float*)d_in[21];
    const float *n2_bw=(const float*)d_in[22],*n2_bb=(const float*)d_in[23];
    const float *mw1=(const float*)d_in[24],  *mb1=(const float*)d_in[25];
    const float *mw2=(const float*)d_in[26],  *mb2=(const float*)d_in[27];

    float* out=(float*)d_out;
    float* out_attn = out + (size_t)ROWS*Ddim;

    SYM(xn,g_xn) SYM(q,g_q) SYM(k,g_k) SYM(v,g_v) SYM(ao,g_ao) SYM(mlph,g_mlph)
    SYM(attn,g_attn) SYM(gq,g_gq) SYM(hbuf,g_h) SYM(sc,g_scale) SYM(sh,g_shift)
    SYM(wq,g_wq) SYM(wk,g_wk) SYM(wv,g_wv) SYM(wo,g_wo) SYM(w1t,g_w1t) SYM(w2t,g_w2t)

    cudaFuncSetAttribute(mma_gemm_pipe, cudaFuncAttributeMaxDynamicSharedMemorySize, PIPESM);

    dim3 tb(32,8);
    tr_round<<<dim3(32,32),tb>>>(wq_w, wq, Ddim, Ddim);
    tr_round<<<dim3(32,32),tb>>>(wk_w, wk, Ddim, Ddim);
    tr_round<<<dim3(32,32),tb>>>(wv_w, wv, Ddim, Ddim);
    tr_round<<<dim3(32,32),tb>>>(out_w, wo, Ddim, Ddim);
    tr_round<<<dim3(128,32),tb>>>(mw1, w1t, Ddim, MLPdim);
    tr_round<<<dim3(32,128),tb>>>(mw2, w2t, MLPdim, Ddim);

    const dim3 sg(4, Bdim);
    small_gemm<<<sg,256>>>(z, n1_hw, n1_hb, hbuf, 1);
    small_gemm<<<sg,256>>>(hbuf, n1_gw, n1_gb, sc, 0);
    small_gemm<<<sg,256>>>(hbuf, n1_bw, n1_bb, sh, 0);
    ln_mod<<<ROWS,256>>>(inputs, sc, sh, xn);

    dim3 g1(8,64);
    mma_gemm_pipe<<<g1,256,PIPESM>>>(xn, wq, wq_b, nullptr, q, Ddim, Ddim, 0);
    mma_gemm_pipe<<<g1,256,PIPESM>>>(xn, wk, wk_b, nullptr, k, Ddim, Ddim, 0);
    mma_gemm_pipe<<<g1,256,PIPESM>>>(xn, wv, wv_b, nullptr, v, Ddim, Ddim, 0);

    qa_kernel<<<ROWS*Hdim/8,256>>>(q, qa_w, qa_b, attn);
    softmax_kernel<<<Bdim*Hdim,256>>>(attn, out_attn);
    globalq_kernel<<<Bdim*Hdim,256>>>(attn, q, gq);
    r_kernel<<<(size_t)ROWS*Ddim/256,256>>>(gq, k, v, q);

    mma_gemm_pipe<<<g1,256,PIPESM>>>(q, wo, out_b, inputs, ao, Ddim, Ddim, 1);

    small_gemm<<<sg,256>>>(z, n2_hw, n2_hb, hbuf, 1);
    small_gemm<<<sg,256>>>(hbuf, n2_gw, n2_gb, sc, 0);
    small_gemm<<<sg,256>>>(hbuf, n2_bw, n2_bb, sh, 0);
    ln_mod<<<ROWS,256>>>(ao, sc, sh, xn);

    dim3 g2(32,64);
    mma_gemm_pipe<<<g2,256,PIPESM>>>(xn, w1t, mb1, nullptr, mlph, MLPdim, Ddim, 2);
    dim3 g3(8,64);
    mma_gemm_pipe<<<g3,256,PIPESM>>>(mlph, w2t, mb2, ao, out, Ddim, MLPdim, 1);
}

// round 9
// speedup vs baseline: 1.6986x; 1.4617x over previous
#include <cuda_runtime.h>
#include <cuda_fp16.h>
#include <math.h>
#include <stdint.h>

#define Bdim 8
#define Ndim 1024
#define Ddim 1024
#define Hdim 16
#define DEPTH 64
#define MLPdim 4096
#define ROWS 8192
#define EPSLN 1e-6f
#define ISD 0.125f

// fp32 buffers
__device__ float g_ao[ROWS*Ddim];
__device__ float g_attn[Bdim*Hdim*Ndim];
__device__ float g_gq[Bdim*Hdim*DEPTH];
__device__ float g_h[Bdim*Ddim];
__device__ float g_scale[Bdim*Ddim];
__device__ float g_shift[Bdim*Ddim];
// fp16 buffers
__device__ __half g_xnh[ROWS*Ddim];
__device__ __half g_qh[ROWS*Ddim];
__device__ __half g_kh[ROWS*Ddim];
__device__ __half g_vh[ROWS*Ddim];
__device__ __half g_mlph[(size_t)ROWS*MLPdim];
__device__ __half g_wqh[Ddim*Ddim];
__device__ __half g_wkh[Ddim*Ddim];
__device__ __half g_wvh[Ddim*Ddim];
__device__ __half g_woh[Ddim*Ddim];
__device__ __half g_w1h[(size_t)Ddim*MLPdim];
__device__ __half g_w2h[(size_t)Ddim*MLPdim];

__device__ __forceinline__ uint32_t cvsm(const void* p){
    uint32_t a; asm("{ .reg .u64 t; cvta.to.shared.u64 t, %1; cvt.u32.u64 %0, t; }":"=r"(a):"l"(p)); return a;
}
__device__ __forceinline__ void cp16(uint32_t d, const void* s){
    asm volatile("cp.async.cg.shared.global [%0], [%1], 16;" :: "r"(d), "l"(s));
}
__device__ __forceinline__ void ldsm4(uint32_t* r, uint32_t a){
    asm volatile("ldmatrix.sync.aligned.m8n8.x4.shared.b16 {%0,%1,%2,%3},[%4];"
        : "=r"(r[0]),"=r"(r[1]),"=r"(r[2]),"=r"(r[3]) : "r"(a));
}
__device__ __forceinline__ void mma_f16(float* d, const uint32_t* a, const uint32_t* b){
    asm volatile(
        "mma.sync.aligned.m16n8k16.row.col.f32.f16.f16.f32 "
        "{%0,%1,%2,%3},{%4,%5,%6,%7},{%8,%9},{%0,%1,%2,%3};"
        : "+f"(d[0]), "+f"(d[1]), "+f"(d[2]), "+f"(d[3])
        : "r"(a[0]), "r"(a[1]), "r"(a[2]), "r"(a[3]), "r"(b[0]), "r"(b[1]));
}

// ---------------- pipelined fp16 mma GEMM, 3-stage, 2 CTA/SM ----------------
// C = epi(A[8192,K]h @ Wt[N,K]h^T + bias_f32); epi 0: half(+b); 1: f32 +b+res; 2: half gelu(+b)
#define ROWB 80                 // bytes per smem row (32 halves + 8 pad)
#define SLOTB 20480             // A 128*80 + B 128*80
#define PIPESM (3*SLOTB)

__device__ __forceinline__ void load_stage(uint32_t smb, const __half* A, const __half* Wt,
    int mBase, int nBase, int Ktot, int kB, int slot, int tid){
    uint32_t st = smb + slot*SLOTB;
    #pragma unroll
    for(int i=0;i<2;++i){
        int idx=i*256+tid, row=idx>>2, cc=idx&3;
        cp16(st + row*ROWB + cc*16, A + (size_t)(mBase+row)*Ktot + kB + cc*8);
    }
    #pragma unroll
    for(int i=0;i<2;++i){
        int idx=i*256+tid, row=idx>>2, cc=idx&3;
        cp16(st + 10240 + row*ROWB + cc*16, Wt + (size_t)(nBase+row)*Ktot + kB + cc*8);
    }
}

template<int EPI>
__global__ __launch_bounds__(256,2)
void hgemm(const __half* __restrict__ A, const __half* __restrict__ Wt,
           const float* __restrict__ bias, const float* __restrict__ res,
           void* __restrict__ Cv, int Ntot, int Ktot){
    extern __shared__ char smraw[];
    const uint32_t smb = cvsm(smraw);
    const int tid = threadIdx.x, lane = tid&31, warp = tid>>5;
    const int wm = warp>>2, wn = warp&3, g = lane>>2, c = lane&3;
    const int mBase = blockIdx.y*128, nBase = blockIdx.x*128;
    const int KS = Ktot/32;

    const uint32_t aoff = (uint32_t)(wm*64 + (lane&15))*ROWB + (uint32_t)(lane>>4)*16;
    const uint32_t boff = 10240u + (uint32_t)(wn*32 + (lane&7) + ((lane>>4)&1)*8)*ROWB
                          + (uint32_t)((lane>>3)&1)*16;

    float acc[4][4][4];
    #pragma unroll
    for(int i=0;i<4;++i)
        #pragma unroll
        for(int j=0;j<4;++j)
            #pragma unroll
            for(int q=0;q<4;++q) acc[i][j][q]=0.f;

    #pragma unroll
    for(int s=0;s<2;++s){
        load_stage(smb, A, Wt, mBase, nBase, Ktot, s*32, s, tid);
        asm volatile("cp.async.commit_group;");
    }

    int slot = 0;
    for(int s=0;s<KS;++s){
        if(s+2<KS){
            int ld = slot+2; if(ld>=3) ld-=3;
            load_stage(smb, A, Wt, mBase, nBase, Ktot, (s+2)*32, ld, tid);
        }
        asm volatile("cp.async.commit_group;");
        asm volatile("cp.async.wait_group 2;");
        __syncthreads();

        const uint32_t sa = smb + (uint32_t)slot*SLOTB;
        #pragma unroll
        for(int ks=0;ks<2;++ks){
            const uint32_t kb = (uint32_t)ks*32;
            uint32_t af[4][4], bf[4][2], bt[4];
            #pragma unroll
            for(int i=0;i<4;++i) ldsm4(af[i], sa + aoff + i*16*ROWB + kb);
            ldsm4(bt, sa + boff + kb);
            bf[0][0]=bt[0]; bf[0][1]=bt[1]; bf[1][0]=bt[2]; bf[1][1]=bt[3];
            ldsm4(bt, sa + boff + 16*ROWB + kb);
            bf[2][0]=bt[0]; bf[2][1]=bt[1]; bf[3][0]=bt[2]; bf[3][1]=bt[3];
            #pragma unroll
            for(int i=0;i<4;++i)
                #pragma unroll
                for(int j=0;j<4;++j)
                    mma_f16(acc[i][j], af[i], bf[j]);
        }
        __syncthreads();
        if(++slot==3) slot=0;
    }

    #pragma unroll
    for(int i=0;i<4;++i){
        const int row0 = mBase + wm*64 + i*16 + g;
        #pragma unroll
        for(int j=0;j<4;++j){
            const int col = nBase + wn*32 + j*8 + 2*c;
            const float b0 = bias[col], b1 = bias[col+1];
            #pragma unroll
            for(int half=0;half<2;++half){
                const int row = row0 + half*8;
                float v0 = acc[i][j][half*2+0] + b0;
                float v1 = acc[i][j][half*2+1] + b1;
                const size_t off = (size_t)row*Ntot + col;
                if(EPI==1){
                    float* Cf = (float*)Cv;
                    const float2 rr = *reinterpret_cast<const float2*>(res + off);
                    float2 o; o.x = v0+rr.x; o.y = v1+rr.y;
                    *reinterpret_cast<float2*>(Cf + off) = o;
                } else {
                    if(EPI==2){
                        v0 = 0.5f*v0*(1.f+erff(v0*0.7071067811865475f));
                        v1 = 0.5f*v1*(1.f+erff(v1*0.7071067811865475f));
                    }
                    __half2* Ch = (__half2*)((__half*)Cv + off);
                    *Ch = __floats2half2_rn(v0, v1);
                }
            }
        }
    }
}

// fp32 in[K,N] -> half out[N,K]
__global__ __launch_bounds__(256)
void trh(const float* __restrict__ in, __half* __restrict__ out, int K, int N){
    __shared__ float t[32][33];
    const int n0 = blockIdx.x*32, k0 = blockIdx.y*32;
    #pragma unroll
    for(int i=0;i<32;i+=8)
        t[threadIdx.y+i][threadIdx.x] = in[(size_t)(k0+threadIdx.y+i)*N + n0+threadIdx.x];
    __syncthreads();
    #pragma unroll
    for(int i=0;i<32;i+=8)
        out[(size_t)(n0+threadIdx.y+i)*K + k0+threadIdx.x] = __float2half_rn(t[threadIdx.x][threadIdx.y+i]);
}

__device__ __forceinline__ float bsum(float v, float* sm){
    #pragma unroll
    for(int o=16;o;o>>=1) v += __shfl_xor_sync(~0u,v,o);
    int wd=threadIdx.x>>5;
    if((threadIdx.x&31)==0) sm[wd]=v;
    __syncthreads();
    float r=0.f;
    if(threadIdx.x<8){ r=sm[threadIdx.x];
        #pragma unroll
        for(int o=4;o;o>>=1) r += __shfl_xor_sync(0xFFu,r,o);
        if(threadIdx.x==0) sm[0]=r; }
    __syncthreads(); r=sm[0]; __syncthreads(); return r;
}
__device__ __forceinline__ float bmax(float v, float* sm){
    #pragma unroll
    for(int o=16;o;o>>=1) v = fmaxf(v,__shfl_xor_sync(~0u,v,o));
    int wd=threadIdx.x>>5;
    if((threadIdx.x&31)==0) sm[wd]=v;
    __syncthreads();
    float r=-1e30f;
    if(threadIdx.x<8){ r=sm[threadIdx.x];
        #pragma unroll
        for(int o=4;o;o>>=1) r = fmaxf(r,__shfl_xor_sync(0xFFu,r,o));
        if(threadIdx.x==0) sm[0]=r; }
    __syncthreads(); r=sm[0]; __syncthreads(); return r;
}

// layernorm + modulation -> half
__global__ __launch_bounds__(256)
void ln_mod(const float* __restrict__ x, const float* __restrict__ sc,
            const float* __restrict__ sh, __half* __restrict__ out){
    __shared__ float sm[8];
    const int row=blockIdx.x, b=row>>10, n=row&1023;
    float4 v = reinterpret_cast<const float4*>(x+(size_t)row*Ddim)[threadIdx.x];
    float mean = bsum(v.x+v.y+v.z+v.w, sm)*(1.f/Ddim);
    float dx=v.x-mean, dy=v.y-mean, dz=v.z-mean, dw=v.w-mean;
    float var = bsum(dx*dx+dy*dy+dz*dz+dw*dw, sm)*(1.f/Ddim);
    float rs = rsqrtf(var+EPSLN);
    float s = sc[b*Ddim+n]*rs, t = sh[b*Ddim+n];
    __half2* o = reinterpret_cast<__half2*>(out+(size_t)row*Ddim) + threadIdx.x*2;
    o[0] = __floats2half2_rn(dx*s+t, dy*s+t);
    o[1] = __floats2half2_rn(dz*s+t, dw*s+t);
}

__global__ __launch_bounds__(256)
void small_gemm(const float* __restrict__ A, const float* __restrict__ W,
                const float* __restrict__ bias, float* __restrict__ out, int act){
    const int n = blockIdx.x*256+threadIdx.x, b = blockIdx.y;
    const float* a = A+(size_t)b*Ddim;
    float acc=0.f;
    for(int k=0;k<Ddim;++k) acc = fmaf(a[k], W[(size_t)k*Ddim+n], acc);
    acc += bias[n];
    if(act) acc = fmaxf(acc,0.f);
    out[(size_t)b*Ddim+n]=acc;
}

__global__ __launch_bounds__(256)
void qa_kernel(const __half* __restrict__ q, const float* __restrict__ w,
               const float* __restrict__ bias, float* __restrict__ attn){
    const int warp=threadIdx.x>>5, lane=threadIdx.x&31;
    const int gi=blockIdx.x*8+warp, hh=gi&15, bn=gi>>4;
    const __half* qr = q+(size_t)bn*Ddim;
    float acc=0.f;
    #pragma unroll 4
    for(int k=lane;k<Ddim;k+=32) acc = fmaf(__half2float(qr[k]), w[k*Hdim+hh], acc);
    #pragma unroll
    for(int o=16;o;o>>=1) acc += __shfl_xor_sync(~0u,acc,o);
    if(lane==0){
        const int b=bn>>10, n=bn&1023;
        attn[(size_t)b*Hdim*Ndim + hh*Ndim + n] = (acc+bias[hh])*ISD;
    }
}

__global__ __launch_bounds__(256)
void softmax_kernel(float* __restrict__ attn, float* __restrict__ oa){
    __shared__ float sm[8];
    const int row=blockIdx.x;
    float4 v = reinterpret_cast<float4*>(attn+(size_t)row*Ndim)[threadIdx.x];
    float m = bmax(fmaxf(fmaxf(v.x,v.y),fmaxf(v.z,v.w)), sm);
    v.x=__expf(v.x-m); v.y=__expf(v.y-m); v.z=__expf(v.z-m); v.w=__expf(v.w-m);
    float s = bsum(v.x+v.y+v.z+v.w, sm);
    const float inv=1.f/s;
    v.x*=inv; v.y*=inv; v.z*=inv; v.w*=inv;
    reinterpret_cast<float4*>(attn+(size_t)row*Ndim)[threadIdx.x]=v;
    reinterpret_cast<float4*>(oa+(size_t)row*Ndim)[threadIdx.x]=v;
}

__global__ __launch_bounds__(256)
void globalq_kernel(const float* __restrict__ attn, const __half* __restrict__ q,
                    float* __restrict__ gq){
    __shared__ float part[256];
    const int bh=blockIdx.x, b=bh>>4, hh=bh&15;
    const int g=threadIdx.x>>6, d=threadIdx.x&63;
    const float* ar = attn+(size_t)bh*Ndim;
    float acc=0.f;
    for(int n=g;n<Ndim;n+=4)
        acc = fmaf(ar[n], __half2float(q[((size_t)(b*Ndim+n))*Ddim + hh*DEPTH + d]), acc);
    part[threadIdx.x]=acc;
    __syncthreads();
    if(g==0) gq[(size_t)bh*DEPTH+d] = part[d]+part[64+d]+part[128+d]+part[192+d];
}

// r = gq*k*v -> half, written in place over v
__global__ __launch_bounds__(256)
void r_kernel(const float* __restrict__ gq, const __half* __restrict__ k,
              __half* __restrict__ v){
    const size_t i = (size_t)blockIdx.x*256+threadIdx.x;
    const int d=(int)(i&1023), b=(int)(i>>20);
    v[i] = __float2half_rn(gq[b*Ddim+d]*__half2float(k[i])*__half2float(v[i]));
}

#define SYMF(p,s) float* p; cudaGetSymbolAddress((void**)&p, s);
#define SYMH(p,s) __half* p; cudaGetSymbolAddress((void**)&p, s);

extern "C" void kernel_launch(void* const* d_in, const int* in_sizes, int n_in,
                              void* d_out, int out_size){
    const float* inputs=(const float*)d_in[0];
    const float* z=(const float*)d_in[1];
    const float *n1_hw=(const float*)d_in[2], *n1_hb=(const float*)d_in[3];
    const float *n1_gw=(const float*)d_in[4], *n1_gb=(const float*)d_in[5];
    const float *n1_bw=(const float*)d_in[6], *n1_bb=(const float*)d_in[7];
    const float *wq_w=(const float*)d_in[8],  *wq_b=(const float*)d_in[9];
    const float *wk_w=(const float*)d_in[10], *wk_b=(const float*)d_in[11];
    const float *wv_w=(const float*)d_in[12], *wv_b=(const float*)d_in[13];
    const float *qa_w=(const float*)d_in[14], *qa_b=(const float*)d_in[15];
    const float *out_w=(const float*)d_in[16],*out_b=(const float*)d_in[17];
    const float *n2_hw=(const float*)d_in[18],*n2_hb=(const float*)d_in[19];
    const float *n2_gw=(const float*)d_in[20],*n2_gb=(const float*)d_in[21];
    const float *n2_bw=(const float*)d_in[22],*n2_bb=(const float*)d_in[23];
    const float *mw1=(const float*)d_in[24],  *mb1=(const float*)d_in[25];
    const float *mw2=(const float*)d_in[26],  *mb2=(const float*)d_in[27];

    float* out=(float*)d_out;
    float* out_attn = out + (size_t)ROWS*Ddim;

    SYMF(ao,g_ao) SYMF(attn,g_attn) SYMF(gq,g_gq) SYMF(hbuf,g_h) SYMF(sc,g_scale) SYMF(sh,g_shift)
    SYMH(xnh,g_xnh) SYMH(qh,g_qh) SYMH(kh,g_kh) SYMH(vh,g_vh) SYMH(mlph,g_mlph)
    SYMH(wqh,g_wqh) SYMH(wkh,g_wkh) SYMH(wvh,g_wvh) SYMH(woh,g_woh) SYMH(w1h,g_w1h) SYMH(w2h,g_w2h)

    cudaFuncSetAttribute(hgemm<0>, cudaFuncAttributeMaxDynamicSharedMemorySize, PIPESM);
    cudaFuncSetAttribute(hgemm<1>, cudaFuncAttributeMaxDynamicSharedMemorySize, PIPESM);
    cudaFuncSetAttribute(hgemm<2>, cudaFuncAttributeMaxDynamicSharedMemorySize, PIPESM);

    dim3 tb(32,8);
    trh<<<dim3(32,32),tb>>>(wq_w, wqh, Ddim, Ddim);
    trh<<<dim3(32,32),tb>>>(wk_w, wkh, Ddim, Ddim);
    trh<<<dim3(32,32),tb>>>(wv_w, wvh, Ddim, Ddim);
    trh<<<dim3(32,32),tb>>>(out_w, woh, Ddim, Ddim);
    trh<<<dim3(128,32),tb>>>(mw1, w1h, Ddim, MLPdim);
    trh<<<dim3(32,128),tb>>>(mw2, w2h, MLPdim, Ddim);

    const dim3 sg(4, Bdim);
    small_gemm<<<sg,256>>>(z, n1_hw, n1_hb, hbuf, 1);
    small_gemm<<<sg,256>>>(hbuf, n1_gw, n1_gb, sc, 0);
    small_gemm<<<sg,256>>>(hbuf, n1_bw, n1_bb, sh, 0);
    ln_mod<<<ROWS,256>>>(inputs, sc, sh, xnh);

    dim3 g1(8,64);
    hgemm<0><<<g1,256,PIPESM>>>(xnh, wqh, wq_b, nullptr, qh, Ddim, Ddim);
    hgemm<0><<<g1,256,PIPESM>>>(xnh, wkh, wk_b, nullptr, kh, Ddim, Ddim);
    hgemm<0><<<g1,256,PIPESM>>>(xnh, wvh, wv_b, nullptr, vh, Ddim, Ddim);

    qa_kernel<<<ROWS*Hdim/8,256>>>(qh, qa_w, qa_b, attn);
    softmax_kernel<<<Bdim*Hdim,256>>>(attn, out_attn);
    globalq_kernel<<<Bdim*Hdim,256>>>(attn, qh, gq);
    r_kernel<<<(size_t)ROWS*Ddim/256,256>>>(gq, kh, vh);

    hgemm<1><<<g1,256,PIPESM>>>(vh, woh, out_b, inputs, ao, Ddim, Ddim);

    small_gemm<<<sg,256>>>(z, n2_hw, n2_hb, hbuf, 1);
    small_gemm<<<sg,256>>>(hbuf, n2_gw, n2_gb, sc, 0);
    small_gemm<<<sg,256>>>(hbuf, n2_bw, n2_bb, sh, 0);
    ln_mod<<<ROWS,256>>>(ao, sc, sh, xnh);

    dim3 g2(32,64);
    hgemm<2><<<g2,256,PIPESM>>>(xnh, w1h, mb1, nullptr, mlph, MLPdim, Ddim);
    dim3 g3(8,64);
    hgemm<1><<<g3,256,PIPESM>>>(mlph, w2h, mb2, ao, out, Ddim, MLPdim);
}

// round 10
// speedup vs baseline: 1.7247x; 1.0154x over previous
#include <cuda_runtime.h>
#include <cuda_fp16.h>
#include <math.h>
#include <stdint.h>

#define Bdim 8
#define Ndim 1024
#define Ddim 1024
#define Hdim 16
#define DEPTH 64
#define MLPdim 4096
#define ROWS 8192
#define EPSLN 1e-6f
#define ISD 0.125f

__device__ float g_ao[ROWS*Ddim];
__device__ float g_attn[Bdim*Hdim*Ndim];
__device__ float g_gq[Bdim*Hdim*DEPTH];
__device__ float g_h[Bdim*Ddim];
__device__ float g_scale[Bdim*Ddim];
__device__ float g_shift[Bdim*Ddim];
__device__ __half g_xnh[ROWS*Ddim];
__device__ __half g_qh[ROWS*Ddim];
__device__ __half g_kh[ROWS*Ddim];
__device__ __half g_vh[ROWS*Ddim];
__device__ __half g_mlph[(size_t)ROWS*MLPdim];
__device__ __half g_wqh[Ddim*Ddim];
__device__ __half g_wkh[Ddim*Ddim];
__device__ __half g_wvh[Ddim*Ddim];
__device__ __half g_woh[Ddim*Ddim];
__device__ __half g_w1h[(size_t)Ddim*MLPdim];
__device__ __half g_w2h[(size_t)Ddim*MLPdim];

__device__ __forceinline__ uint32_t cvsm(const void* p){
    uint32_t a; asm("{ .reg .u64 t; cvta.to.shared.u64 t, %1; cvt.u32.u64 %0, t; }":"=r"(a):"l"(p)); return a;
}
__device__ __forceinline__ void cp16(uint32_t d, const void* s){
    asm volatile("cp.async.cg.shared.global [%0], [%1], 16;" :: "r"(d), "l"(s));
}
__device__ __forceinline__ void ldsm4(uint32_t* r, uint32_t a){
    asm volatile("ldmatrix.sync.aligned.m8n8.x4.shared.b16 {%0,%1,%2,%3},[%4];"
        : "=r"(r[0]),"=r"(r[1]),"=r"(r[2]),"=r"(r[3]) : "r"(a));
}
__device__ __forceinline__ void mma_f16(float* d, const uint32_t* a, const uint32_t* b){
    asm volatile(
        "mma.sync.aligned.m16n8k16.row.col.f32.f16.f16.f32 "
        "{%0,%1,%2,%3},{%4,%5,%6,%7},{%8,%9},{%0,%1,%2,%3};"
        : "+f"(d[0]), "+f"(d[1]), "+f"(d[2]), "+f"(d[3])
        : "r"(a[0]), "r"(a[1]), "r"(a[2]), "r"(a[3]), "r"(b[0]), "r"(b[1]));
}

// ---------------- fp16 mma GEMM: CTA 128x256, warp 64x64, 4-stage, 1 sync/chunk ----------------
#define ROWB 80                 // 32 halves + 16B pad
#define AB 10240                // A tile bytes per stage (128*80)
#define SLOTB 30720             // A + B(256*80)
#define NSTAGE 4
#define PIPESM (NSTAGE*SLOTB)

__device__ __forceinline__ void load_stage(uint32_t smb, const __half* A, const __half* Wt,
    int mBase, int nBase, int Ktot, int kB, int slot, int tid){
    uint32_t st = smb + slot*SLOTB;
    #pragma unroll
    for(int i=0;i<2;++i){
        int idx=i*256+tid, row=idx>>2, cc=idx&3;
        cp16(st + row*ROWB + cc*16, A + (size_t)(mBase+row)*Ktot + kB + cc*8);
    }
    #pragma unroll
    for(int i=0;i<4;++i){
        int idx=i*256+tid, row=idx>>2, cc=idx&3;
        cp16(st + AB + row*ROWB + cc*16, Wt + (size_t)(nBase+row)*Ktot + kB + cc*8);
    }
}

template<int EPI>
__global__ __launch_bounds__(256,1)
void hgemm(const __half* __restrict__ A, const __half* __restrict__ Wt,
           const float* __restrict__ bias, const float* __restrict__ res,
           void* __restrict__ Cv, int Ntot, int Ktot){
    extern __shared__ char smraw[];
    const uint32_t smb = cvsm(smraw);
    const int tid = threadIdx.x, lane = tid&31, warp = tid>>5;
    const int wm = warp>>2, wn = warp&3, g = lane>>2, c = lane&3;
    const int mBase = blockIdx.y*128, nBase = blockIdx.x*256;
    const int KS = Ktot/32;

    const uint32_t aoff = (uint32_t)(wm*64 + (lane&15))*ROWB + (uint32_t)(lane>>4)*16;
    const uint32_t boff = AB + (uint32_t)(wn*64 + (lane&7) + ((lane>>4)&1)*8)*ROWB
                          + (uint32_t)((lane>>3)&1)*16;

    float acc[4][8][4];
    #pragma unroll
    for(int i=0;i<4;++i)
        #pragma unroll
        for(int j=0;j<8;++j)
            #pragma unroll
            for(int q=0;q<4;++q) acc[i][j][q]=0.f;

    #pragma unroll
    for(int s=0;s<NSTAGE-1;++s){
        load_stage(smb, A, Wt, mBase, nBase, Ktot, s*32, s, tid);
        asm volatile("cp.async.commit_group;");
    }

    int slot = 0;
    for(int s=0;s<KS;++s){
        asm volatile("cp.async.wait_group %0;" :: "n"(NSTAGE-2));
        __syncthreads();
        const uint32_t sa = smb + (uint32_t)slot*SLOTB;

        // ---- k16 #0: load frags ----
        uint32_t af[4][4], bf[8][2], bt[4];
        #pragma unroll
        for(int i=0;i<4;++i) ldsm4(af[i], sa + aoff + i*16*ROWB);
        #pragma unroll
        for(int jj=0;jj<4;++jj){
            ldsm4(bt, sa + boff + jj*16*ROWB);
            bf[2*jj][0]=bt[0]; bf[2*jj][1]=bt[1]; bf[2*jj+1][0]=bt[2]; bf[2*jj+1][1]=bt[3];
        }
        // prefetch next stage while MMAs run
        if(s+NSTAGE-1<KS){
            int ld = slot+NSTAGE-1; if(ld>=NSTAGE) ld-=NSTAGE;
            load_stage(smb, A, Wt, mBase, nBase, Ktot, (s+NSTAGE-1)*32, ld, tid);
        }
        asm volatile("cp.async.commit_group;");
        #pragma unroll
        for(int i=0;i<4;++i)
            #pragma unroll
            for(int j=0;j<8;++j)
                mma_f16(acc[i][j], af[i], bf[j]);

        // ---- k16 #1 ----
        #pragma unroll
        for(int i=0;i<4;++i) ldsm4(af[i], sa + aoff + i*16*ROWB + 32);
        #pragma unroll
        for(int jj=0;jj<4;++jj){
            ldsm4(bt, sa + boff + jj*16*ROWB + 32);
            bf[2*jj][0]=bt[0]; bf[2*jj][1]=bt[1]; bf[2*jj+1][0]=bt[2]; bf[2*jj+1][1]=bt[3];
        }
        #pragma unroll
        for(int i=0;i<4;++i)
            #pragma unroll
            for(int j=0;j<8;++j)
                mma_f16(acc[i][j], af[i], bf[j]);

        if(++slot==NSTAGE) slot=0;
    }

    #pragma unroll
    for(int i=0;i<4;++i){
        const int row0 = mBase + wm*64 + i*16 + g;
        #pragma unroll
        for(int j=0;j<8;++j){
            const int col = nBase + wn*64 + j*8 + 2*c;
            const float b0 = bias[col], b1 = bias[col+1];
            #pragma unroll
            for(int half=0;half<2;++half){
                const int row = row0 + half*8;
                float v0 = acc[i][j][half*2+0] + b0;
                float v1 = acc[i][j][half*2+1] + b1;
                const size_t off = (size_t)row*Ntot + col;
                if(EPI==1){
                    float* Cf = (float*)Cv;
                    const float2 rr = *reinterpret_cast<const float2*>(res + off);
                    float2 o; o.x = v0+rr.x; o.y = v1+rr.y;
                    *reinterpret_cast<float2*>(Cf + off) = o;
                } else {
                    if(EPI==2){
                        v0 = 0.5f*v0*(1.f+erff(v0*0.7071067811865475f));
                        v1 = 0.5f*v1*(1.f+erff(v1*0.7071067811865475f));
                    }
                    __half2* Ch = (__half2*)((__half*)Cv + off);
                    *Ch = __floats2half2_rn(v0, v1);
                }
            }
        }
    }
}

__global__ __launch_bounds__(256)
void trh(const float* __restrict__ in, __half* __restrict__ out, int K, int N){
    __shared__ float t[32][33];
    const int n0 = blockIdx.x*32, k0 = blockIdx.y*32;
    #pragma unroll
    for(int i=0;i<32;i+=8)
        t[threadIdx.y+i][threadIdx.x] = in[(size_t)(k0+threadIdx.y+i)*N + n0+threadIdx.x];
    __syncthreads();
    #pragma unroll
    for(int i=0;i<32;i+=8)
        out[(size_t)(n0+threadIdx.y+i)*K + k0+threadIdx.x] = __float2half_rn(t[threadIdx.x][threadIdx.y+i]);
}

__device__ __forceinline__ float bsum(float v, float* sm){
    #pragma unroll
    for(int o=16;o;o>>=1) v += __shfl_xor_sync(~0u,v,o);
    int wd=threadIdx.x>>5;
    if((threadIdx.x&31)==0) sm[wd]=v;
    __syncthreads();
    float r=0.f;
    if(threadIdx.x<8){ r=sm[threadIdx.x];
        #pragma unroll
        for(int o=4;o;o>>=1) r += __shfl_xor_sync(0xFFu,r,o);
        if(threadIdx.x==0) sm[0]=r; }
    __syncthreads(); r=sm[0]; __syncthreads(); return r;
}
__device__ __forceinline__ float bmax(float v, float* sm){
    #pragma unroll
    for(int o=16;o;o>>=1) v = fmaxf(v,__shfl_xor_sync(~0u,v,o));
    int wd=threadIdx.x>>5;
    if((threadIdx.x&31)==0) sm[wd]=v;
    __syncthreads();
    float r=-1e30f;
    if(threadIdx.x<8){ r=sm[threadIdx.x];
        #pragma unroll
        for(int o=4;o;o>>=1) r = fmaxf(r,__shfl_xor_sync(0xFFu,r,o));
        if(threadIdx.x==0) sm[0]=r; }
    __syncthreads(); r=sm[0]; __syncthreads(); return r;
}

__global__ __launch_bounds__(256)
void ln_mod(const float* __restrict__ x, const float* __restrict__ sc,
            const float* __restrict__ sh, __half* __restrict__ out){
    __shared__ float sm[8];
    const int row=blockIdx.x, b=row>>10, n=row&1023;
    float4 v = reinterpret_cast<const float4*>(x+(size_t)row*Ddim)[threadIdx.x];
    float mean = bsum(v.x+v.y+v.z+v.w, sm)*(1.f/Ddim);
    float dx=v.x-mean, dy=v.y-mean, dz=v.z-mean, dw=v.w-mean;
    float var = bsum(dx*dx+dy*dy+dz*dz+dw*dw, sm)*(1.f/Ddim);
    float rs = rsqrtf(var+EPSLN);
    float s = sc[b*Ddim+n]*rs, t = sh[b*Ddim+n];
    __half2* o = reinterpret_cast<__half2*>(out+(size_t)row*Ddim) + threadIdx.x*2;
    o[0] = __floats2half2_rn(dx*s+t, dy*s+t);
    o[1] = __floats2half2_rn(dz*s+t, dw*s+t);
}

__global__ __launch_bounds__(256)
void small_gemm(const float* __restrict__ A, const float* __restrict__ W,
                const float* __restrict__ bias, float* __restrict__ out, int act){
    const int n = blockIdx.x*256+threadIdx.x, b = blockIdx.y;
    const float* a = A+(size_t)b*Ddim;
    float acc=0.f;
    for(int k=0;k<Ddim;++k) acc = fmaf(a[k], W[(size_t)k*Ddim+n], acc);
    acc += bias[n];
    if(act) acc = fmaxf(acc,0.f);
    out[(size_t)b*Ddim+n]=acc;
}

__global__ __launch_bounds__(256)
void qa_kernel(const __half* __restrict__ q, const float* __restrict__ w,
               const float* __restrict__ bias, float* __restrict__ attn){
    const int warp=threadIdx.x>>5, lane=threadIdx.x&31;
    const int gi=blockIdx.x*8+warp, hh=gi&15, bn=gi>>4;
    const __half* qr = q+(size_t)bn*Ddim;
    float acc=0.f;
    #pragma unroll 4
    for(int k=lane;k<Ddim;k+=32) acc = fmaf(__half2float(qr[k]), w[k*Hdim+hh], acc);
    #pragma unroll
    for(int o=16;o;o>>=1) acc += __shfl_xor_sync(~0u,acc,o);
    if(lane==0){
        const int b=bn>>10, n=bn&1023;
        attn[(size_t)b*Hdim*Ndim + hh*Ndim + n] = (acc+bias[hh])*ISD;
    }
}

__global__ __launch_bounds__(256)
void softmax_kernel(float* __restrict__ attn, float* __restrict__ oa){
    __shared__ float sm[8];
    const int row=blockIdx.x;
    float4 v = reinterpret_cast<float4*>(attn+(size_t)row*Ndim)[threadIdx.x];
    float m = bmax(fmaxf(fmaxf(v.x,v.y),fmaxf(v.z,v.w)), sm);
    v.x=__expf(v.x-m); v.y=__expf(v.y-m); v.z=__expf(v.z-m); v.w=__expf(v.w-m);
    float s = bsum(v.x+v.y+v.z+v.w, sm);
    const float inv=1.f/s;
    v.x*=inv; v.y*=inv; v.z*=inv; v.w*=inv;
    reinterpret_cast<float4*>(attn+(size_t)row*Ndim)[threadIdx.x]=v;
    reinterpret_cast<float4*>(oa+(size_t)row*Ndim)[threadIdx.x]=v;
}

__global__ __launch_bounds__(256)
void globalq_kernel(const float* __restrict__ attn, const __half* __restrict__ q,
                    float* __restrict__ gq){
    __shared__ float part[256];
    const int bh=blockIdx.x, b=bh>>4, hh=bh&15;
    const int g=threadIdx.x>>6, d=threadIdx.x&63;
    const float* ar = attn+(size_t)bh*Ndim;
    float acc=0.f;
    for(int n=g;n<Ndim;n+=4)
        acc = fmaf(ar[n], __half2float(q[((size_t)(b*Ndim+n))*Ddim + hh*DEPTH + d]), acc);
    part[threadIdx.x]=acc;
    __syncthreads();
    if(g==0) gq[(size_t)bh*DEPTH+d] = part[d]+part[64+d]+part[128+d]+part[192+d];
}

__global__ __launch_bounds__(256)
void r_kernel(const float* __restrict__ gq, const __half* __restrict__ k,
              __half* __restrict__ v){
    const size_t i = (size_t)blockIdx.x*256+threadIdx.x;
    const int d=(int)(i&1023), b=(int)(i>>20);
    v[i] = __float2half_rn(gq[b*Ddim+d]*__half2float(k[i])*__half2float(v[i]));
}

#define SYMF(p,s) float* p; cudaGetSymbolAddress((void**)&p, s);
#define SYMH(p,s) __half* p; cudaGetSymbolAddress((void**)&p, s);

extern "C" void kernel_launch(void* const* d_in, const int* in_sizes, int n_in,
                              void* d_out, int out_size){
    const float* inputs=(const float*)d_in[0];
    const float* z=(const float*)d_in[1];
    const float *n1_hw=(const float*)d_in[2], *n1_hb=(const float*)d_in[3];
    const float *n1_gw=(const float*)d_in[4], *n1_gb=(const float*)d_in[5];
    const float *n1_bw=(const float*)d_in[6], *n1_bb=(const float*)d_in[7];
    const float *wq_w=(const float*)d_in[8],  *wq_b=(const float*)d_in[9];
    const float *wk_w=(const float*)d_in[10], *wk_b=(const float*)d_in[11];
    const float *wv_w=(const float*)d_in[12], *wv_b=(const float*)d_in[13];
    const float *qa_w=(const float*)d_in[14], *qa_b=(const float*)d_in[15];
    const float *out_w=(const float*)d_in[16],*out_b=(const float*)d_in[17];
    const float *n2_hw=(const float*)d_in[18],*n2_hb=(const float*)d_in[19];
    const float *n2_gw=(const float*)d_in[20],*n2_gb=(const float*)d_in[21];
    const float *n2_bw=(const float*)d_in[22],*n2_bb=(const float*)d_in[23];
    const float *mw1=(const float*)d_in[24],  *mb1=(const float*)d_in[25];
    const float *mw2=(const float*)d_in[26],  *mb2=(const float*)d_in[27];

    float* out=(float*)d_out;
    float* out_attn = out + (size_t)ROWS*Ddim;

    SYMF(ao,g_ao) SYMF(attn,g_attn) SYMF(gq,g_gq) SYMF(hbuf,g_h) SYMF(sc,g_scale) SYMF(sh,g_shift)
    SYMH(xnh,g_xnh) SYMH(qh,g_qh) SYMH(kh,g_kh) SYMH(vh,g_vh) SYMH(mlph,g_mlph)
    SYMH(wqh,g_wqh) SYMH(wkh,g_wkh) SYMH(wvh,g_wvh) SYMH(woh,g_woh) SYMH(w1h,g_w1h) SYMH(w2h,g_w2h)

    cudaFuncSetAttribute(hgemm<0>, cudaFuncAttributeMaxDynamicSharedMemorySize, PIPESM);
    cudaFuncSetAttribute(hgemm<1>, cudaFuncAttributeMaxDynamicSharedMemorySize, PIPESM);
    cudaFuncSetAttribute(hgemm<2>, cudaFuncAttributeMaxDynamicSharedMemorySize, PIPESM);

    dim3 tb(32,8);
    trh<<<dim3(32,32),tb>>>(wq_w, wqh, Ddim, Ddim);
    trh<<<dim3(32,32),tb>>>(wk_w, wkh, Ddim, Ddim);
    trh<<<dim3(32,32),tb>>>(wv_w, wvh, Ddim, Ddim);
    trh<<<dim3(32,32),tb>>>(out_w, woh, Ddim, Ddim);
    trh<<<dim3(128,32),tb>>>(mw1, w1h, Ddim, MLPdim);
    trh<<<dim3(32,128),tb>>>(mw2, w2h, MLPdim, Ddim);

    const dim3 sg(4, Bdim);
    small_gemm<<<sg,256>>>(z, n1_hw, n1_hb, hbuf, 1);
    small_gemm<<<sg,256>>>(hbuf, n1_gw, n1_gb, sc, 0);
    small_gemm<<<sg,256>>>(hbuf, n1_bw, n1_bb, sh, 0);
    ln_mod<<<ROWS,256>>>(inputs, sc, sh, xnh);

    dim3 g1(4,64);
    hgemm<0><<<g1,256,PIPESM>>>(xnh, wqh, wq_b, nullptr, qh, Ddim, Ddim);
    hgemm<0><<<g1,256,PIPESM>>>(xnh, wkh, wk_b, nullptr, kh, Ddim, Ddim);
    hgemm<0><<<g1,256,PIPESM>>>(xnh, wvh, wv_b, nullptr, vh, Ddim, Ddim);

    qa_kernel<<<ROWS*Hdim/8,256>>>(qh, qa_w, qa_b, attn);
    softmax_kernel<<<Bdim*Hdim,256>>>(attn, out_attn);
    globalq_kernel<<<Bdim*Hdim,256>>>(attn, qh, gq);
    r_kernel<<<(size_t)ROWS*Ddim/256,256>>>(gq, kh, vh);

    hgemm<1><<<g1,256,PIPESM>>>(vh, woh, out_b, inputs, ao, Ddim, Ddim);

    small_gemm<<<sg,256>>>(z, n2_hw, n2_hb, hbuf, 1);
    small_gemm<<<sg,256>>>(hbuf, n2_gw, n2_gb, sc, 0);
    small_gemm<<<sg,256>>>(hbuf, n2_bw, n2_bb, sh, 0);
    ln_mod<<<ROWS,256>>>(ao, sc, sh, xnh);

    dim3 g2(16,64);
    hgemm<2><<<g2,256,PIPESM>>>(xnh, w1h, mb1, nullptr, mlph, MLPdim, Ddim);
    dim3 g3(4,64);
    hgemm<1><<<g3,256,PIPESM>>>(mlph, w2h, mb2, ao, out, Ddim, MLPdim);
}